// round 10
// baseline (speedup 1.0000x reference)
#include <cuda_runtime.h>
#include <cuda_bf16.h>
#include <cstdint>

#define V_SIZE 50257
#define E_SIZE 768
#define QK_SIZE 256
#define B_SIZE 4
#define T_SIZE 1024
#define M_ROWS (B_SIZE * T_SIZE)   // 4096
#define LN_EPS 1e-5f

#define BM 128
#define BN 256
#define BK 64                         // 64 bf16 = 128B rows (xor-swizzled)
#define KIT (E_SIZE / BK)             // 12 k-slices
// stage: Ah 16K | Al 16K | Bh 32K | Bl 32K = 96KB
#define STAGE_BYTES 98304
#define SMEM_DYN (2 * STAGE_BYTES)    // 192KB, 2-stage pipeline

// ---------------- scratch (static device memory; no allocation) ----------------
__device__ __align__(256) float g_x[M_ROWS * E_SIZE];
__device__ __align__(256) float g_q[M_ROWS * QK_SIZE];
__device__ __align__(256) float g_k[M_ROWS * QK_SIZE];
__device__ __align__(256) float g_c[(size_t)B_SIZE * T_SIZE * T_SIZE];  // 16MB QK^T
__device__ __align__(256) __nv_bfloat16 g_xh[M_ROWS * E_SIZE];
__device__ __align__(256) __nv_bfloat16 g_xl[M_ROWS * E_SIZE];
__device__ __align__(256) __nv_bfloat16 g_wh[(size_t)V_SIZE * E_SIZE];
__device__ __align__(256) __nv_bfloat16 g_wl[(size_t)V_SIZE * E_SIZE];

// ---------------- PTX helpers (generic PTX only — no sm_103a features) --------
__device__ __forceinline__ uint32_t smem_u32(const void* p) {
    uint32_t a;
    asm("{ .reg .u64 t; cvta.to.shared.u64 t, %1; cvt.u32.u64 %0, t; }" : "=r"(a) : "l"(p));
    return a;
}
__device__ __forceinline__ void cp16(uint32_t dst, const void* src) {
    asm volatile("cp.async.cg.shared.global [%0], [%1], 16;" :: "r"(dst), "l"(src));
}
#define CP_COMMIT() asm volatile("cp.async.commit_group;" ::: "memory")
#define CP_WAIT1()  asm volatile("cp.async.wait_group 1;" ::: "memory")
#define CP_WAIT0()  asm volatile("cp.async.wait_group 0;" ::: "memory")

__device__ __forceinline__ void ldsm_x4(uint32_t& r0, uint32_t& r1, uint32_t& r2, uint32_t& r3,
                                        uint32_t addr) {
    asm volatile("ldmatrix.sync.aligned.m8n8.x4.shared.b16 {%0,%1,%2,%3}, [%4];"
                 : "=r"(r0), "=r"(r1), "=r"(r2), "=r"(r3) : "r"(addr));
}
__device__ __forceinline__ void mma16816(float* d, const uint32_t* a, const uint32_t* b) {
    asm volatile("mma.sync.aligned.m16n8k16.row.col.f32.bf16.bf16.f32 "
                 "{%0,%1,%2,%3}, {%4,%5,%6,%7}, {%8,%9}, {%0,%1,%2,%3};"
                 : "+f"(d[0]), "+f"(d[1]), "+f"(d[2]), "+f"(d[3])
                 : "r"(a[0]), "r"(a[1]), "r"(a[2]), "r"(a[3]), "r"(b[0]), "r"(b[1]));
}
// swizzled byte offset inside a tile with 128B rows: row r, 16B-chunk c
__device__ __forceinline__ uint32_t swz(int r, int c) {
    return (uint32_t)(r * 128 + ((c ^ (r & 7)) << 4));
}

// ---------------- kernel 0: gather + layernorm (+ bf16 hi/lo split of x) ------
__global__ void ln_kernel(const int* __restrict__ idx,
                          const float* __restrict__ emb,
                          const float* __restrict__ gamma,
                          const float* __restrict__ beta,
                          float* __restrict__ xout) {
    int r = blockIdx.x;
    int tok = idx[r];
    const float* e = emb + (size_t)tok * E_SIZE;
    int tid = threadIdx.x;

    float v[3];
    float s = 0.f;
#pragma unroll
    for (int j = 0; j < 3; j++) { v[j] = e[tid + j * 256]; s += v[j]; }

    __shared__ float red[8];
    __shared__ float sh_mu, sh_inv;
#pragma unroll
    for (int o = 16; o > 0; o >>= 1) s += __shfl_xor_sync(0xffffffffu, s, o);
    if ((tid & 31) == 0) red[tid >> 5] = s;
    __syncthreads();
    if (tid == 0) {
        float tot = 0.f;
#pragma unroll
        for (int w = 0; w < 8; w++) tot += red[w];
        sh_mu = tot * (1.f / E_SIZE);
    }
    __syncthreads();
    float mu = sh_mu;

    float s2 = 0.f;
#pragma unroll
    for (int j = 0; j < 3; j++) { float d = v[j] - mu; s2 += d * d; }
#pragma unroll
    for (int o = 16; o > 0; o >>= 1) s2 += __shfl_xor_sync(0xffffffffu, s2, o);
    if ((tid & 31) == 0) red[tid >> 5] = s2;
    __syncthreads();
    if (tid == 0) {
        float tot = 0.f;
#pragma unroll
        for (int w = 0; w < 8; w++) tot += red[w];
        sh_inv = rsqrtf(tot * (1.f / E_SIZE) + LN_EPS);
    }
    __syncthreads();
    float inv = sh_inv;

#pragma unroll
    for (int j = 0; j < 3; j++) {
        int i = tid + j * 256;
        float y = (v[j] - mu) * inv * gamma[i] + beta[i];
        size_t o = (size_t)r * E_SIZE + i;
        g_x[o] = y;
        __nv_bfloat16 h = __float2bfloat16(y);
        g_xh[o] = h;
        g_xl[o] = __float2bfloat16(y - __bfloat162float(h));
        if (xout) xout[o] = y;
    }
}

// ---------------- kernel 0b: split head_w into bf16 hi/lo ----------------
__global__ void wsplit_kernel(const float* __restrict__ w) {
    size_t i2 = (size_t)blockIdx.x * blockDim.x + threadIdx.x;
    size_t n2 = (size_t)V_SIZE * E_SIZE / 2;
    if (i2 >= n2) return;
    float2 v = ((const float2*)w)[i2];
    __nv_bfloat16 h0 = __float2bfloat16(v.x);
    __nv_bfloat16 h1 = __float2bfloat16(v.y);
    __nv_bfloat16 l0 = __float2bfloat16(v.x - __bfloat162float(h0));
    __nv_bfloat16 l1 = __float2bfloat16(v.y - __bfloat162float(h1));
    ((__nv_bfloat162*)g_wh)[i2] = __nv_bfloat162(h0, h1);
    ((__nv_bfloat162*)g_wl)[i2] = __nv_bfloat162(l0, l1);
}

// ---------------- kernel 1: bf16 mma.sync vocab GEMM, operand-shared 3 passes -
// Per k-slice, SMEM stage holds {xh, xl, wh, wl} tiles ONCE; computes
// xh*wh + xl*wh + xh*wl into one fp32 accumulator. BM=128, BN=256, 8 warps.
__global__ __launch_bounds__(256, 1)
void mma_gemm_kernel(const __nv_bfloat16* __restrict__ xh,
                     const __nv_bfloat16* __restrict__ xl,
                     const __nv_bfloat16* __restrict__ wh,
                     const __nv_bfloat16* __restrict__ wl,
                     float* __restrict__ C) {
    extern __shared__ char smem[];
    const uint32_t sb = smem_u32(smem);

    const int tid = threadIdx.x;
    const int wid = tid >> 5;
    const int lane = tid & 31;
    const int m0 = blockIdx.x * BM;
    const int n0 = blockIdx.y * BN;

    const int wm = (wid & 1) * 64;     // 2 warps in M (64 each)
    const int wn = (wid >> 1) * 64;    // 4 warps in N (64 each)

    float acc[4][8][4];
#pragma unroll
    for (int mi = 0; mi < 4; mi++)
#pragma unroll
        for (int ni = 0; ni < 8; ni++)
#pragma unroll
            for (int q = 0; q < 4; q++) acc[mi][ni][q] = 0.f;

    auto load_stage = [&](int kit, int slot) {
        int kbase = kit * BK;
        uint32_t st = sb + slot * STAGE_BYTES;
        uint32_t ah = st, al = st + 16384, bh = st + 32768, bl = st + 65536;
        // A tiles: 128 rows x 8 chunks -> 4 per thread each
#pragma unroll
        for (int j = 0; j < 4; j++) {
            int id = tid + j * 256;
            int r = id >> 3, c = id & 7;
            size_t go = (size_t)(m0 + r) * E_SIZE + kbase + c * 8;
            cp16(ah + swz(r, c), xh + go);
            cp16(al + swz(r, c), xl + go);
        }
        // B tiles: 256 rows x 8 chunks -> 8 per thread each (clamp tail rows)
#pragma unroll
        for (int j = 0; j < 8; j++) {
            int id = tid + j * 256;
            int r = id >> 3, c = id & 7;
            int gn = n0 + r;
            if (gn > V_SIZE - 1) gn = V_SIZE - 1;
            size_t go = (size_t)gn * E_SIZE + kbase + c * 8;
            cp16(bh + swz(r, c), wh + go);
            cp16(bl + swz(r, c), wl + go);
        }
        CP_COMMIT();
    };

    load_stage(0, 0);
    load_stage(1, 1);

    const int lrl = lane & 7;
    const int lmat = lane >> 3;

    for (int t = 0; t < KIT; t++) {
        if (t < KIT - 2) { CP_WAIT1(); } else { CP_WAIT0(); }
        __syncthreads();
        uint32_t st = sb + (t & 1) * STAGE_BYTES;
        uint32_t ah_s = st, al_s = st + 16384, bh_s = st + 32768, bl_s = st + 65536;

#pragma unroll
        for (int kk = 0; kk < 4; kk++) {            // 4 x k16 per k-slice
            int cbase = kk * 2;
            uint32_t afh[4][4], afl[4][4], bfr[8][2];
            // A-hi fragments (4 m16 tiles)
#pragma unroll
            for (int mi = 0; mi < 4; mi++) {
                int r = wm + mi * 16 + lrl + (lmat & 1) * 8;
                int c = cbase + (lmat >> 1);
                ldsm_x4(afh[mi][0], afh[mi][1], afh[mi][2], afh[mi][3], ah_s + swz(r, c));
            }
            // B-hi fragments (8 n8 tiles)
#pragma unroll
            for (int pr = 0; pr < 4; pr++) {
                int r = wn + pr * 16 + lrl + (lmat >> 1) * 8;
                int c = cbase + (lmat & 1);
                uint32_t q0, q1, q2, q3;
                ldsm_x4(q0, q1, q2, q3, bh_s + swz(r, c));
                bfr[pr * 2 + 0][0] = q0; bfr[pr * 2 + 0][1] = q1;
                bfr[pr * 2 + 1][0] = q2; bfr[pr * 2 + 1][1] = q3;
            }
            // pass 1: xh * wh
#pragma unroll
            for (int mi = 0; mi < 4; mi++)
#pragma unroll
                for (int ni = 0; ni < 8; ni++)
                    mma16816(acc[mi][ni], afh[mi], bfr[ni]);
            // A-lo fragments
#pragma unroll
            for (int mi = 0; mi < 4; mi++) {
                int r = wm + mi * 16 + lrl + (lmat & 1) * 8;
                int c = cbase + (lmat >> 1);
                ldsm_x4(afl[mi][0], afl[mi][1], afl[mi][2], afl[mi][3], al_s + swz(r, c));
            }
            // pass 2: xl * wh
#pragma unroll
            for (int mi = 0; mi < 4; mi++)
#pragma unroll
                for (int ni = 0; ni < 8; ni++)
                    mma16816(acc[mi][ni], afl[mi], bfr[ni]);
            // B-lo fragments (overwrite bfr)
#pragma unroll
            for (int pr = 0; pr < 4; pr++) {
                int r = wn + pr * 16 + lrl + (lmat >> 1) * 8;
                int c = cbase + (lmat & 1);
                uint32_t q0, q1, q2, q3;
                ldsm_x4(q0, q1, q2, q3, bl_s + swz(r, c));
                bfr[pr * 2 + 0][0] = q0; bfr[pr * 2 + 0][1] = q1;
                bfr[pr * 2 + 1][0] = q2; bfr[pr * 2 + 1][1] = q3;
            }
            // pass 3: xh * wl
#pragma unroll
            for (int mi = 0; mi < 4; mi++)
#pragma unroll
                for (int ni = 0; ni < 8; ni++)
                    mma16816(acc[mi][ni], afh[mi], bfr[ni]);
        }
        __syncthreads();          // all warps done with this buffer
        if (t + 2 < KIT) load_stage(t + 2, t & 1);
    }

    // scalar stores: V_SIZE odd -> odd rows only 4B-aligned
    const int lr = lane >> 2;
    const int lc = (lane & 3) * 2;
#pragma unroll
    for (int mi = 0; mi < 4; mi++) {
        int row0 = m0 + wm + mi * 16 + lr;
#pragma unroll
        for (int ni = 0; ni < 8; ni++) {
            int col = n0 + wn + ni * 8 + lc;
            float* d0 = C + (size_t)row0 * V_SIZE + col;
            float* d1 = C + (size_t)(row0 + 8) * V_SIZE + col;
            if (col < V_SIZE)     { d0[0] = acc[mi][ni][0]; d1[0] = acc[mi][ni][2]; }
            if (col + 1 < V_SIZE) { d0[1] = acc[mi][ni][1]; d1[1] = acc[mi][ni][3]; }
        }
    }
}

// ---------------- kernel 2: fused q+k projections (fp32 SGEMM, z selects) -----
__global__ __launch_bounds__(256, 2)
void qkproj_kernel(const float* __restrict__ A,
                   const float* __restrict__ Wq,
                   const float* __restrict__ Wk) {
    const int K = E_SIZE;
    __shared__ float As[16][128];
    __shared__ float Bs[16][128];

    const float* W = blockIdx.z ? Wk : Wq;
    float* C = blockIdx.z ? g_k : g_q;

    int tid = threadIdx.x;
    int m0 = blockIdx.y * 128;
    int n0 = blockIdx.x * 128;

    float acc[8][8];
#pragma unroll
    for (int i = 0; i < 8; i++)
#pragma unroll
        for (int j = 0; j < 8; j++) acc[i][j] = 0.f;

    int lrow = tid >> 2;
    int lk = (tid & 3) * 4;

    for (int k0 = 0; k0 < K; k0 += 16) {
#pragma unroll
        for (int l = 0; l < 2; l++) {
            int row = lrow + l * 64;
            float4 va = *(const float4*)(A + (size_t)(m0 + row) * K + k0 + lk);
            As[lk + 0][row] = va.x; As[lk + 1][row] = va.y;
            As[lk + 2][row] = va.z; As[lk + 3][row] = va.w;
            float4 vb = *(const float4*)(W + (size_t)(n0 + row) * K + k0 + lk);
            Bs[lk + 0][row] = vb.x; Bs[lk + 1][row] = vb.y;
            Bs[lk + 2][row] = vb.z; Bs[lk + 3][row] = vb.w;
        }
        __syncthreads();

        int mth = (tid >> 4) * 8;
        int nth = (tid & 15) * 8;
#pragma unroll
        for (int kk = 0; kk < 16; kk++) {
            float4 a0 = *(const float4*)&As[kk][mth];
            float4 a1 = *(const float4*)&As[kk][mth + 4];
            float4 b0 = *(const float4*)&Bs[kk][nth];
            float4 b1 = *(const float4*)&Bs[kk][nth + 4];
            float a[8] = {a0.x, a0.y, a0.z, a0.w, a1.x, a1.y, a1.z, a1.w};
            float b[8] = {b0.x, b0.y, b0.z, b0.w, b1.x, b1.y, b1.z, b1.w};
#pragma unroll
            for (int i = 0; i < 8; i++)
#pragma unroll
                for (int j = 0; j < 8; j++) acc[i][j] = fmaf(a[i], b[j], acc[i][j]);
        }
        __syncthreads();
    }

    int mrow = m0 + (tid >> 4) * 8;
    int ncol = n0 + (tid & 15) * 8;
#pragma unroll
    for (int i = 0; i < 8; i++) {
        float* crow = C + (size_t)(mrow + i) * QK_SIZE;
#pragma unroll
        for (int j = 0; j < 8; j++) crow[ncol + j] = acc[i][j];
    }
}

// ---------------- kernel 3: c = q k^T  (lower-triangle tiles only) ------------
__global__ __launch_bounds__(256, 2)
void qk_gemm_kernel() {
    int bx = blockIdx.x;
    int b = bx / 36;
    int p = bx % 36;
    int mt = 0;
    while ((mt + 1) * (mt + 2) / 2 <= p) mt++;
    int nt = p - mt * (mt + 1) / 2;

    const float* Aq = g_q + (size_t)b * T_SIZE * QK_SIZE;
    const float* Bk = g_k + (size_t)b * T_SIZE * QK_SIZE;
    float* C = g_c + (size_t)b * T_SIZE * T_SIZE;

    __shared__ float As[16][128];
    __shared__ float Bs[16][128];

    int tid = threadIdx.x;
    int m0 = mt * 128;
    int n0 = nt * 128;

    float acc[8][8];
#pragma unroll
    for (int i = 0; i < 8; i++)
#pragma unroll
        for (int j = 0; j < 8; j++) acc[i][j] = 0.f;

    int lrow = tid >> 2;
    int lk = (tid & 3) * 4;

    for (int k0 = 0; k0 < QK_SIZE; k0 += 16) {
#pragma unroll
        for (int l = 0; l < 2; l++) {
            int row = lrow + l * 64;
            float4 va = *(const float4*)(Aq + (size_t)(m0 + row) * QK_SIZE + k0 + lk);
            As[lk + 0][row] = va.x; As[lk + 1][row] = va.y;
            As[lk + 2][row] = va.z; As[lk + 3][row] = va.w;
            float4 vb = *(const float4*)(Bk + (size_t)(n0 + row) * QK_SIZE + k0 + lk);
            Bs[lk + 0][row] = vb.x; Bs[lk + 1][row] = vb.y;
            Bs[lk + 2][row] = vb.z; Bs[lk + 3][row] = vb.w;
        }
        __syncthreads();

        int mth = (tid >> 4) * 8;
        int nth = (tid & 15) * 8;
#pragma unroll
        for (int kk = 0; kk < 16; kk++) {
            float4 a0 = *(const float4*)&As[kk][mth];
            float4 a1 = *(const float4*)&As[kk][mth + 4];
            float4 b0 = *(const float4*)&Bs[kk][nth];
            float4 b1 = *(const float4*)&Bs[kk][nth + 4];
            float a[8] = {a0.x, a0.y, a0.z, a0.w, a1.x, a1.y, a1.z, a1.w};
            float b[8] = {b0.x, b0.y, b0.z, b0.w, b1.x, b1.y, b1.z, b1.w};
#pragma unroll
            for (int i = 0; i < 8; i++)
#pragma unroll
                for (int j = 0; j < 8; j++) acc[i][j] = fmaf(a[i], b[j], acc[i][j]);
        }
        __syncthreads();
    }

    int mrow = m0 + (tid >> 4) * 8;
    int ncol = n0 + (tid & 15) * 8;
#pragma unroll
    for (int i = 0; i < 8; i++) {
        float* crow = C + (size_t)(mrow + i) * T_SIZE;
#pragma unroll
        for (int j = 0; j < 8; j++) crow[ncol + j] = acc[i][j];
    }
}

// ---------------- kernel 4: scatter-add  logits[r, idx[b,s]] += c[r,s]/QK -----
__global__ void scatter_kernel(const int* __restrict__ idx,
                               float* __restrict__ logits) {
    int r = blockIdx.x;
    int b = r >> 10;
    int t = r & 1023;

    const float* crow = g_c + (size_t)b * T_SIZE * T_SIZE + (size_t)t * T_SIZE;
    const int* ib = idx + b * T_SIZE;
    float* lrow = logits + (size_t)r * V_SIZE;

    for (int s = threadIdx.x; s <= t; s += blockDim.x)
        atomicAdd(&lrow[ib[s]], crow[s] * (1.0f / QK_SIZE));
}

// ---------------- launch ----------------
extern "C" void kernel_launch(void* const* d_in, const int* in_sizes, int n_in,
                              void* d_out, int out_size) {
    const int*   idx    = (const int*)d_in[0];
    const float* emb_w  = (const float*)d_in[1];
    const float* ln_g   = (const float*)d_in[2];
    const float* ln_b   = (const float*)d_in[3];
    const float* head_w = (const float*)d_in[4];
    const float* head_q = (const float*)d_in[5];
    const float* head_k = (const float*)d_in[6];

    void *px, *pxh, *pxl, *pwh, *pwl;
    cudaGetSymbolAddress(&px, g_x);
    cudaGetSymbolAddress(&pxh, g_xh);
    cudaGetSymbolAddress(&pxl, g_xl);
    cudaGetSymbolAddress(&pwh, g_wh);
    cudaGetSymbolAddress(&pwl, g_wl);

    float* out    = (float*)d_out;
    float* logits = out;

    const size_t logits_elems = (size_t)M_ROWS * V_SIZE;
    const size_t x_elems      = (size_t)M_ROWS * E_SIZE;
    float* xout = nullptr;
    if ((size_t)out_size >= logits_elems + x_elems)
        xout = out + ((size_t)out_size - x_elems);

    // 1) x = layernorm(emb[idx]) (+ bf16 hi/lo split of x)
    ln_kernel<<<M_ROWS, 256>>>(idx, emb_w, ln_g, ln_b, xout);

    // 1b) split head_w into bf16 hi/lo
    {
        size_t n2 = (size_t)V_SIZE * E_SIZE / 2;
        wsplit_kernel<<<(unsigned)((n2 + 255) / 256), 256>>>(head_w);
    }

    // 2) fused q+k projections (z dim selects target)
    {
        dim3 grid(QK_SIZE / 128, M_ROWS / 128, 2);
        qkproj_kernel<<<grid, 256>>>((float*)px, head_q, head_k);
    }

    // 3) c = q k^T lower-triangle tiles into g_c
    qk_gemm_kernel<<<B_SIZE * 36, 256>>>();

    // 4) logits = x @ head_w^T via operand-shared bf16 mma.sync (3 products)
    {
        cudaFuncSetAttribute(mma_gemm_kernel, cudaFuncAttributeMaxDynamicSharedMemorySize, SMEM_DYN);
        dim3 grid(M_ROWS / BM, (V_SIZE + BN - 1) / BN);   // x fastest: B-tile L2 reuse
        mma_gemm_kernel<<<grid, 256, SMEM_DYN>>>(
            (const __nv_bfloat16*)pxh, (const __nv_bfloat16*)pxl,
            (const __nv_bfloat16*)pwh, (const __nv_bfloat16*)pwl, logits);
    }

    // 5) causal copy-scatter from precomputed c
    scatter_kernel<<<M_ROWS, 256>>>(idx, logits);
}

// round 11
// speedup vs baseline: 1.4344x; 1.4344x over previous
#include <cuda_runtime.h>
#include <cuda_bf16.h>
#include <cuda_fp16.h>
#include <cstdint>

#define V_SIZE 50257
#define E_SIZE 768
#define QK_SIZE 256
#define B_SIZE 4
#define T_SIZE 1024
#define M_ROWS (B_SIZE * T_SIZE)   // 4096
#define LN_EPS 1e-5f

#define BM 128
#define BN 128
#define BK 64                          // 64 fp16 = 128B rows (xor-swizzled)
#define KIT (E_SIZE / BK)              // 12 k-slices
// stage: Ah 16K | Al 16K | B 16K = 48KB; 2 stages = 96KB -> 2 CTAs/SM
#define STAGE_BYTES 49152
#define SMEM_DYN (2 * STAGE_BYTES)

// ---------------- scratch (static device memory; no allocation) ----------------
__device__ __align__(256) float g_x[M_ROWS * E_SIZE];
__device__ __align__(256) float g_q[M_ROWS * QK_SIZE];
__device__ __align__(256) float g_k[M_ROWS * QK_SIZE];
__device__ __align__(256) float g_c[(size_t)B_SIZE * T_SIZE * T_SIZE];  // 16MB QK^T
__device__ __align__(256) __half g_xh[M_ROWS * E_SIZE];
__device__ __align__(256) __half g_xl[M_ROWS * E_SIZE];
__device__ __align__(256) __half g_wh[(size_t)V_SIZE * E_SIZE];

// ---------------- PTX helpers (generic PTX only — no sm_103a features) --------
__device__ __forceinline__ uint32_t smem_u32(const void* p) {
    uint32_t a;
    asm("{ .reg .u64 t; cvta.to.shared.u64 t, %1; cvt.u32.u64 %0, t; }" : "=r"(a) : "l"(p));
    return a;
}
__device__ __forceinline__ void cp16(uint32_t dst, const void* src) {
    asm volatile("cp.async.cg.shared.global [%0], [%1], 16;" :: "r"(dst), "l"(src));
}
#define CP_COMMIT() asm volatile("cp.async.commit_group;" ::: "memory")
#define CP_WAIT1()  asm volatile("cp.async.wait_group 1;" ::: "memory")
#define CP_WAIT0()  asm volatile("cp.async.wait_group 0;" ::: "memory")

__device__ __forceinline__ void ldsm_x4(uint32_t& r0, uint32_t& r1, uint32_t& r2, uint32_t& r3,
                                        uint32_t addr) {
    asm volatile("ldmatrix.sync.aligned.m8n8.x4.shared.b16 {%0,%1,%2,%3}, [%4];"
                 : "=r"(r0), "=r"(r1), "=r"(r2), "=r"(r3) : "r"(addr));
}
__device__ __forceinline__ void mma16816(float* d, const uint32_t* a, const uint32_t* b) {
    asm volatile("mma.sync.aligned.m16n8k16.row.col.f32.f16.f16.f32 "
                 "{%0,%1,%2,%3}, {%4,%5,%6,%7}, {%8,%9}, {%0,%1,%2,%3};"
                 : "+f"(d[0]), "+f"(d[1]), "+f"(d[2]), "+f"(d[3])
                 : "r"(a[0]), "r"(a[1]), "r"(a[2]), "r"(a[3]), "r"(b[0]), "r"(b[1]));
}
// swizzled byte offset inside a tile with 128B rows: row r, 16B-chunk c
__device__ __forceinline__ uint32_t swz(int r, int c) {
    return (uint32_t)(r * 128 + ((c ^ (r & 7)) << 4));
}

// ---------------- kernel 0: gather + layernorm (+ fp16 hi/lo split of x) ------
__global__ void ln_kernel(const int* __restrict__ idx,
                          const float* __restrict__ emb,
                          const float* __restrict__ gamma,
                          const float* __restrict__ beta,
                          float* __restrict__ xout) {
    int r = blockIdx.x;
    int tok = idx[r];
    const float* e = emb + (size_t)tok * E_SIZE;
    int tid = threadIdx.x;

    float v[3];
    float s = 0.f;
#pragma unroll
    for (int j = 0; j < 3; j++) { v[j] = e[tid + j * 256]; s += v[j]; }

    __shared__ float red[8];
    __shared__ float sh_mu, sh_inv;
#pragma unroll
    for (int o = 16; o > 0; o >>= 1) s += __shfl_xor_sync(0xffffffffu, s, o);
    if ((tid & 31) == 0) red[tid >> 5] = s;
    __syncthreads();
    if (tid == 0) {
        float tot = 0.f;
#pragma unroll
        for (int w = 0; w < 8; w++) tot += red[w];
        sh_mu = tot * (1.f / E_SIZE);
    }
    __syncthreads();
    float mu = sh_mu;

    float s2 = 0.f;
#pragma unroll
    for (int j = 0; j < 3; j++) { float d = v[j] - mu; s2 += d * d; }
#pragma unroll
    for (int o = 16; o > 0; o >>= 1) s2 += __shfl_xor_sync(0xffffffffu, s2, o);
    if ((tid & 31) == 0) red[tid >> 5] = s2;
    __syncthreads();
    if (tid == 0) {
        float tot = 0.f;
#pragma unroll
        for (int w = 0; w < 8; w++) tot += red[w];
        sh_inv = rsqrtf(tot * (1.f / E_SIZE) + LN_EPS);
    }
    __syncthreads();
    float inv = sh_inv;

#pragma unroll
    for (int j = 0; j < 3; j++) {
        int i = tid + j * 256;
        float y = (v[j] - mu) * inv * gamma[i] + beta[i];
        size_t o = (size_t)r * E_SIZE + i;
        g_x[o] = y;
        __half h = __float2half_rn(y);
        g_xh[o] = h;
        g_xl[o] = __float2half_rn(y - __half2float(h));
        if (xout) xout[o] = y;
    }
}

// ---------------- kernel 0b: head_w -> fp16 ----------------
__global__ void wsplit_kernel(const float* __restrict__ w) {
    size_t i2 = (size_t)blockIdx.x * blockDim.x + threadIdx.x;
    size_t n2 = (size_t)V_SIZE * E_SIZE / 2;
    if (i2 >= n2) return;
    float2 v = ((const float2*)w)[i2];
    __half2 h = __floats2half2_rn(v.x, v.y);
    ((__half2*)g_wh)[i2] = h;
}

// ---------------- kernel 1: fp16 mma.sync vocab GEMM, shared-B 2 passes -------
// C[m0:+128, n0:+128] = xh*wh^T + xl*wh^T   (fp32 accum)
// Stage holds {xh, xl, wh} tiles; B fragments reused across both passes.
__global__ __launch_bounds__(256)
void mma_gemm_kernel(const __half* __restrict__ xh,
                     const __half* __restrict__ xl,
                     const __half* __restrict__ wh,
                     float* __restrict__ C) {
    extern __shared__ char smem[];
    const uint32_t sb = smem_u32(smem);

    const int tid = threadIdx.x;
    const int wid = tid >> 5;
    const int lane = tid & 31;
    const int m0 = blockIdx.x * BM;
    const int n0 = blockIdx.y * BN;

    const int wm = (wid & 3) * 32;   // 4 warps in M (32 each)
    const int wn = (wid >> 2) * 64;  // 2 warps in N (64 each)

    float acc[2][8][4];
#pragma unroll
    for (int mi = 0; mi < 2; mi++)
#pragma unroll
        for (int ni = 0; ni < 8; ni++)
#pragma unroll
            for (int q = 0; q < 4; q++) acc[mi][ni][q] = 0.f;

    auto load_stage = [&](int kit, int slot) {
        int kbase = kit * BK;
        uint32_t st = sb + slot * STAGE_BYTES;
        uint32_t ah = st, al = st + 16384, bs = st + 32768;
        // A tiles (xh and xl): 128 rows x 8 chunks each -> 4 per thread each
#pragma unroll
        for (int j = 0; j < 4; j++) {
            int id = tid + j * 256;
            int r = id >> 3, c = id & 7;
            size_t go = (size_t)(m0 + r) * E_SIZE + kbase + c * 8;
            cp16(ah + swz(r, c), xh + go);
            cp16(al + swz(r, c), xl + go);
        }
        // B tile (wh): 128 rows x 8 chunks -> 4 per thread (clamp tail rows)
#pragma unroll
        for (int j = 0; j < 4; j++) {
            int id = tid + j * 256;
            int r = id >> 3, c = id & 7;
            int gn = n0 + r;
            if (gn > V_SIZE - 1) gn = V_SIZE - 1;
            cp16(bs + swz(r, c), wh + (size_t)gn * E_SIZE + kbase + c * 8);
        }
        CP_COMMIT();
    };

    load_stage(0, 0);
    load_stage(1, 1);

    const int lrl = lane & 7;
    const int lmat = lane >> 3;

    for (int t = 0; t < KIT; t++) {
        if (t < KIT - 2) { CP_WAIT1(); } else { CP_WAIT0(); }
        __syncthreads();
        uint32_t st = sb + (t & 1) * STAGE_BYTES;
        uint32_t ah_s = st, al_s = st + 16384, b_s = st + 32768;

#pragma unroll
        for (int kk = 0; kk < 4; kk++) {            // 4 x k16 per k-slice
            int cbase = kk * 2;
            // B fragments: 8 n8 tiles (shared across both passes)
            uint32_t bfr[8][2];
#pragma unroll
            for (int pr = 0; pr < 4; pr++) {
                int r = wn + pr * 16 + lrl + (lmat >> 1) * 8;
                int c = cbase + (lmat & 1);
                uint32_t q0, q1, q2, q3;
                ldsm_x4(q0, q1, q2, q3, b_s + swz(r, c));
                bfr[pr * 2 + 0][0] = q0; bfr[pr * 2 + 0][1] = q1;
                bfr[pr * 2 + 1][0] = q2; bfr[pr * 2 + 1][1] = q3;
            }
            // A-hi fragments + pass 1: xh * wh
            uint32_t afr[2][4];
#pragma unroll
            for (int mi = 0; mi < 2; mi++) {
                int r = wm + mi * 16 + lrl + (lmat & 1) * 8;
                int c = cbase + (lmat >> 1);
                ldsm_x4(afr[mi][0], afr[mi][1], afr[mi][2], afr[mi][3], ah_s + swz(r, c));
            }
#pragma unroll
            for (int mi = 0; mi < 2; mi++)
#pragma unroll
                for (int ni = 0; ni < 8; ni++)
                    mma16816(acc[mi][ni], afr[mi], bfr[ni]);
            // A-lo fragments + pass 2: xl * wh
#pragma unroll
            for (int mi = 0; mi < 2; mi++) {
                int r = wm + mi * 16 + lrl + (lmat & 1) * 8;
                int c = cbase + (lmat >> 1);
                ldsm_x4(afr[mi][0], afr[mi][1], afr[mi][2], afr[mi][3], al_s + swz(r, c));
            }
#pragma unroll
            for (int mi = 0; mi < 2; mi++)
#pragma unroll
                for (int ni = 0; ni < 8; ni++)
                    mma16816(acc[mi][ni], afr[mi], bfr[ni]);
        }
        __syncthreads();
        if (t + 2 < KIT) load_stage(t + 2, t & 1);
    }

    // scalar stores: V_SIZE odd -> odd rows only 4B-aligned
    const int lr = lane >> 2;
    const int lc = (lane & 3) * 2;
#pragma unroll
    for (int mi = 0; mi < 2; mi++) {
        int row0 = m0 + wm + mi * 16 + lr;
#pragma unroll
        for (int ni = 0; ni < 8; ni++) {
            int col = n0 + wn + ni * 8 + lc;
            float* d0 = C + (size_t)row0 * V_SIZE + col;
            float* d1 = C + (size_t)(row0 + 8) * V_SIZE + col;
            if (col < V_SIZE)     { d0[0] = acc[mi][ni][0]; d1[0] = acc[mi][ni][2]; }
            if (col + 1 < V_SIZE) { d0[1] = acc[mi][ni][1]; d1[1] = acc[mi][ni][3]; }
        }
    }
}

// ---------------- kernel 2: fused q+k projections (fp32 SGEMM, z selects) -----
__global__ __launch_bounds__(256, 2)
void qkproj_kernel(const float* __restrict__ A,
                   const float* __restrict__ Wq,
                   const float* __restrict__ Wk) {
    const int K = E_SIZE;
    __shared__ float As[16][128];
    __shared__ float Bs[16][128];

    const float* W = blockIdx.z ? Wk : Wq;
    float* C = blockIdx.z ? g_k : g_q;

    int tid = threadIdx.x;
    int m0 = blockIdx.y * 128;
    int n0 = blockIdx.x * 128;

    float acc[8][8];
#pragma unroll
    for (int i = 0; i < 8; i++)
#pragma unroll
        for (int j = 0; j < 8; j++) acc[i][j] = 0.f;

    int lrow = tid >> 2;
    int lk = (tid & 3) * 4;

    for (int k0 = 0; k0 < K; k0 += 16) {
#pragma unroll
        for (int l = 0; l < 2; l++) {
            int row = lrow + l * 64;
            float4 va = *(const float4*)(A + (size_t)(m0 + row) * K + k0 + lk);
            As[lk + 0][row] = va.x; As[lk + 1][row] = va.y;
            As[lk + 2][row] = va.z; As[lk + 3][row] = va.w;
            float4 vb = *(const float4*)(W + (size_t)(n0 + row) * K + k0 + lk);
            Bs[lk + 0][row] = vb.x; Bs[lk + 1][row] = vb.y;
            Bs[lk + 2][row] = vb.z; Bs[lk + 3][row] = vb.w;
        }
        __syncthreads();

        int mth = (tid >> 4) * 8;
        int nth = (tid & 15) * 8;
#pragma unroll
        for (int kk = 0; kk < 16; kk++) {
            float4 a0 = *(const float4*)&As[kk][mth];
            float4 a1 = *(const float4*)&As[kk][mth + 4];
            float4 b0 = *(const float4*)&Bs[kk][nth];
            float4 b1 = *(const float4*)&Bs[kk][nth + 4];
            float a[8] = {a0.x, a0.y, a0.z, a0.w, a1.x, a1.y, a1.z, a1.w};
            float b[8] = {b0.x, b0.y, b0.z, b0.w, b1.x, b1.y, b1.z, b1.w};
#pragma unroll
            for (int i = 0; i < 8; i++)
#pragma unroll
                for (int j = 0; j < 8; j++) acc[i][j] = fmaf(a[i], b[j], acc[i][j]);
        }
        __syncthreads();
    }

    int mrow = m0 + (tid >> 4) * 8;
    int ncol = n0 + (tid & 15) * 8;
#pragma unroll
    for (int i = 0; i < 8; i++) {
        float* crow = C + (size_t)(mrow + i) * QK_SIZE;
#pragma unroll
        for (int j = 0; j < 8; j++) crow[ncol + j] = acc[i][j];
    }
}

// ---------------- kernel 3: c = q k^T  (lower-triangle tiles only) ------------
__global__ __launch_bounds__(256, 2)
void qk_gemm_kernel() {
    int bx = blockIdx.x;
    int b = bx / 36;
    int p = bx % 36;
    int mt = 0;
    while ((mt + 1) * (mt + 2) / 2 <= p) mt++;
    int nt = p - mt * (mt + 1) / 2;

    const float* Aq = g_q + (size_t)b * T_SIZE * QK_SIZE;
    const float* Bk = g_k + (size_t)b * T_SIZE * QK_SIZE;
    float* C = g_c + (size_t)b * T_SIZE * T_SIZE;

    __shared__ float As[16][128];
    __shared__ float Bs[16][128];

    int tid = threadIdx.x;
    int m0 = mt * 128;
    int n0 = nt * 128;

    float acc[8][8];
#pragma unroll
    for (int i = 0; i < 8; i++)
#pragma unroll
        for (int j = 0; j < 8; j++) acc[i][j] = 0.f;

    int lrow = tid >> 2;
    int lk = (tid & 3) * 4;

    for (int k0 = 0; k0 < QK_SIZE; k0 += 16) {
#pragma unroll
        for (int l = 0; l < 2; l++) {
            int row = lrow + l * 64;
            float4 va = *(const float4*)(Aq + (size_t)(m0 + row) * QK_SIZE + k0 + lk);
            As[lk + 0][row] = va.x; As[lk + 1][row] = va.y;
            As[lk + 2][row] = va.z; As[lk + 3][row] = va.w;
            float4 vb = *(const float4*)(Bk + (size_t)(n0 + row) * QK_SIZE + k0 + lk);
            Bs[lk + 0][row] = vb.x; Bs[lk + 1][row] = vb.y;
            Bs[lk + 2][row] = vb.z; Bs[lk + 3][row] = vb.w;
        }
        __syncthreads();

        int mth = (tid >> 4) * 8;
        int nth = (tid & 15) * 8;
#pragma unroll
        for (int kk = 0; kk < 16; kk++) {
            float4 a0 = *(const float4*)&As[kk][mth];
            float4 a1 = *(const float4*)&As[kk][mth + 4];
            float4 b0 = *(const float4*)&Bs[kk][nth];
            float4 b1 = *(const float4*)&Bs[kk][nth + 4];
            float a[8] = {a0.x, a0.y, a0.z, a0.w, a1.x, a1.y, a1.z, a1.w};
            float b[8] = {b0.x, b0.y, b0.z, b0.w, b1.x, b1.y, b1.z, b1.w};
#pragma unroll
            for (int i = 0; i < 8; i++)
#pragma unroll
                for (int j = 0; j < 8; j++) acc[i][j] = fmaf(a[i], b[j], acc[i][j]);
        }
        __syncthreads();
    }

    int mrow = m0 + (tid >> 4) * 8;
    int ncol = n0 + (tid & 15) * 8;
#pragma unroll
    for (int i = 0; i < 8; i++) {
        float* crow = C + (size_t)(mrow + i) * T_SIZE;
#pragma unroll
        for (int j = 0; j < 8; j++) crow[ncol + j] = acc[i][j];
    }
}

// ---------------- kernel 4: scatter-add  logits[r, idx[b,s]] += c[r,s]/QK -----
__global__ void scatter_kernel(const int* __restrict__ idx,
                               float* __restrict__ logits) {
    int r = blockIdx.x;
    int b = r >> 10;
    int t = r & 1023;

    const float* crow = g_c + (size_t)b * T_SIZE * T_SIZE + (size_t)t * T_SIZE;
    const int* ib = idx + b * T_SIZE;
    float* lrow = logits + (size_t)r * V_SIZE;

    for (int s = threadIdx.x; s <= t; s += blockDim.x)
        atomicAdd(&lrow[ib[s]], crow[s] * (1.0f / QK_SIZE));
}

// ---------------- launch ----------------
extern "C" void kernel_launch(void* const* d_in, const int* in_sizes, int n_in,
                              void* d_out, int out_size) {
    const int*   idx    = (const int*)d_in[0];
    const float* emb_w  = (const float*)d_in[1];
    const float* ln_g   = (const float*)d_in[2];
    const float* ln_b   = (const float*)d_in[3];
    const float* head_w = (const float*)d_in[4];
    const float* head_q = (const float*)d_in[5];
    const float* head_k = (const float*)d_in[6];

    void *px, *pxh, *pxl, *pwh;
    cudaGetSymbolAddress(&px, g_x);
    cudaGetSymbolAddress(&pxh, g_xh);
    cudaGetSymbolAddress(&pxl, g_xl);
    cudaGetSymbolAddress(&pwh, g_wh);

    float* out    = (float*)d_out;
    float* logits = out;

    const size_t logits_elems = (size_t)M_ROWS * V_SIZE;
    const size_t x_elems      = (size_t)M_ROWS * E_SIZE;
    float* xout = nullptr;
    if ((size_t)out_size >= logits_elems + x_elems)
        xout = out + ((size_t)out_size - x_elems);

    // 1) x = layernorm(emb[idx]) (+ fp16 hi/lo split of x)
    ln_kernel<<<M_ROWS, 256>>>(idx, emb_w, ln_g, ln_b, xout);

    // 1b) head_w -> fp16
    {
        size_t n2 = (size_t)V_SIZE * E_SIZE / 2;
        wsplit_kernel<<<(unsigned)((n2 + 255) / 256), 256>>>(head_w);
    }

    // 2) fused q+k projections
    {
        dim3 grid(QK_SIZE / 128, M_ROWS / 128, 2);
        qkproj_kernel<<<grid, 256>>>((float*)px, head_q, head_k);
    }

    // 3) c = q k^T lower-triangle tiles into g_c
    qk_gemm_kernel<<<B_SIZE * 36, 256>>>();

    // 4) logits = x @ head_w^T via fp16 mma.sync, shared-B 2-pass split
    {
        cudaFuncSetAttribute(mma_gemm_kernel, cudaFuncAttributeMaxDynamicSharedMemorySize, SMEM_DYN);
        dim3 grid(M_ROWS / BM, (V_SIZE + BN - 1) / BN);
        mma_gemm_kernel<<<grid, 256, SMEM_DYN>>>(
            (const __half*)pxh, (const __half*)pxl, (const __half*)pwh, logits);
    }

    // 5) causal copy-scatter from precomputed c
    scatter_kernel<<<M_ROWS, 256>>>(idx, logits);
}

// round 12
// speedup vs baseline: 2.0301x; 1.4153x over previous
#include <cuda_runtime.h>
#include <cuda_bf16.h>
#include <cuda_fp16.h>
#include <cstdint>

#define V_SIZE 50257
#define E_SIZE 768
#define QK_SIZE 256
#define B_SIZE 4
#define T_SIZE 1024
#define M_ROWS (B_SIZE * T_SIZE)   // 4096
#define LN_EPS 1e-5f

#define BM 128
#define BN 128
#define BK 64                          // 64 fp16 = 128B rows (xor-swizzled)
#define KIT (E_SIZE / BK)              // 12 k-slices
// stage: A 16K | B 16K = 32KB; 2 stages = 64KB
#define STAGE_BYTES 32768
#define SMEM_DYN (2 * STAGE_BYTES)

// ---------------- scratch (static device memory; no allocation) ----------------
__device__ __align__(256) float g_x[M_ROWS * E_SIZE];
__device__ __align__(256) float g_q[M_ROWS * QK_SIZE];
__device__ __align__(256) float g_k[M_ROWS * QK_SIZE];
__device__ __align__(256) float g_c[(size_t)B_SIZE * T_SIZE * T_SIZE];  // 16MB QK^T
__device__ __align__(256) __half g_xh[M_ROWS * E_SIZE];
__device__ __align__(256) __half g_wh[(size_t)V_SIZE * E_SIZE];

// ---------------- PTX helpers (generic PTX only — no sm_103a features) --------
__device__ __forceinline__ uint32_t smem_u32(const void* p) {
    uint32_t a;
    asm("{ .reg .u64 t; cvta.to.shared.u64 t, %1; cvt.u32.u64 %0, t; }" : "=r"(a) : "l"(p));
    return a;
}
__device__ __forceinline__ void cp16(uint32_t dst, const void* src) {
    asm volatile("cp.async.cg.shared.global [%0], [%1], 16;" :: "r"(dst), "l"(src));
}
#define CP_COMMIT() asm volatile("cp.async.commit_group;" ::: "memory")
#define CP_WAIT1()  asm volatile("cp.async.wait_group 1;" ::: "memory")
#define CP_WAIT0()  asm volatile("cp.async.wait_group 0;" ::: "memory")

__device__ __forceinline__ void ldsm_x4(uint32_t& r0, uint32_t& r1, uint32_t& r2, uint32_t& r3,
                                        uint32_t addr) {
    asm volatile("ldmatrix.sync.aligned.m8n8.x4.shared.b16 {%0,%1,%2,%3}, [%4];"
                 : "=r"(r0), "=r"(r1), "=r"(r2), "=r"(r3) : "r"(addr));
}
__device__ __forceinline__ void mma16816(float* d, const uint32_t* a, const uint32_t* b) {
    asm volatile("mma.sync.aligned.m16n8k16.row.col.f32.f16.f16.f32 "
                 "{%0,%1,%2,%3}, {%4,%5,%6,%7}, {%8,%9}, {%0,%1,%2,%3};"
                 : "+f"(d[0]), "+f"(d[1]), "+f"(d[2]), "+f"(d[3])
                 : "r"(a[0]), "r"(a[1]), "r"(a[2]), "r"(a[3]), "r"(b[0]), "r"(b[1]));
}
// swizzled byte offset inside a tile with 128B rows: row r, 16B-chunk c
__device__ __forceinline__ uint32_t swz(int r, int c) {
    return (uint32_t)(r * 128 + ((c ^ (r & 7)) << 4));
}

// ---------------- kernel 0: gather + layernorm (+ fp16 copy of x) -------------
__global__ void ln_kernel(const int* __restrict__ idx,
                          const float* __restrict__ emb,
                          const float* __restrict__ gamma,
                          const float* __restrict__ beta,
                          float* __restrict__ xout) {
    int r = blockIdx.x;
    int tok = idx[r];
    const float* e = emb + (size_t)tok * E_SIZE;
    int tid = threadIdx.x;

    float v[3];
    float s = 0.f;
#pragma unroll
    for (int j = 0; j < 3; j++) { v[j] = e[tid + j * 256]; s += v[j]; }

    __shared__ float red[8];
    __shared__ float sh_mu, sh_inv;
#pragma unroll
    for (int o = 16; o > 0; o >>= 1) s += __shfl_xor_sync(0xffffffffu, s, o);
    if ((tid & 31) == 0) red[tid >> 5] = s;
    __syncthreads();
    if (tid == 0) {
        float tot = 0.f;
#pragma unroll
        for (int w = 0; w < 8; w++) tot += red[w];
        sh_mu = tot * (1.f / E_SIZE);
    }
    __syncthreads();
    float mu = sh_mu;

    float s2 = 0.f;
#pragma unroll
    for (int j = 0; j < 3; j++) { float d = v[j] - mu; s2 += d * d; }
#pragma unroll
    for (int o = 16; o > 0; o >>= 1) s2 += __shfl_xor_sync(0xffffffffu, s2, o);
    if ((tid & 31) == 0) red[tid >> 5] = s2;
    __syncthreads();
    if (tid == 0) {
        float tot = 0.f;
#pragma unroll
        for (int w = 0; w < 8; w++) tot += red[w];
        sh_inv = rsqrtf(tot * (1.f / E_SIZE) + LN_EPS);
    }
    __syncthreads();
    float inv = sh_inv;

#pragma unroll
    for (int j = 0; j < 3; j++) {
        int i = tid + j * 256;
        float y = (v[j] - mu) * inv * gamma[i] + beta[i];
        size_t o = (size_t)r * E_SIZE + i;
        g_x[o] = y;
        g_xh[o] = __float2half_rn(y);
        if (xout) xout[o] = y;
    }
}

// ---------------- kernel 0b: head_w -> fp16 ----------------
__global__ void wsplit_kernel(const float* __restrict__ w) {
    size_t i2 = (size_t)blockIdx.x * blockDim.x + threadIdx.x;
    size_t n2 = (size_t)V_SIZE * E_SIZE / 2;
    if (i2 >= n2) return;
    float2 v = ((const float2*)w)[i2];
    ((__half2*)g_wh)[i2] = __floats2half2_rn(v.x, v.y);
}

// ---------------- kernel 1: fp16 mma.sync vocab GEMM (single pass) ------------
// C[m0:+128, n0:+128] = xh*wh^T   (fp32 accum)
__global__ __launch_bounds__(256)
void mma_gemm_kernel(const __half* __restrict__ xh,
                     const __half* __restrict__ wh,
                     float* __restrict__ C) {
    extern __shared__ char smem[];
    const uint32_t sb = smem_u32(smem);

    const int tid = threadIdx.x;
    const int wid = tid >> 5;
    const int lane = tid & 31;
    const int m0 = blockIdx.x * BM;
    const int n0 = blockIdx.y * BN;

    const int wm = (wid & 3) * 32;   // 4 warps in M (32 each)
    const int wn = (wid >> 2) * 64;  // 2 warps in N (64 each)

    float acc[2][8][4];
#pragma unroll
    for (int mi = 0; mi < 2; mi++)
#pragma unroll
        for (int ni = 0; ni < 8; ni++)
#pragma unroll
            for (int q = 0; q < 4; q++) acc[mi][ni][q] = 0.f;

    auto load_stage = [&](int kit, int slot) {
        int kbase = kit * BK;
        uint32_t st = sb + slot * STAGE_BYTES;
        uint32_t as = st, bs = st + 16384;
#pragma unroll
        for (int j = 0; j < 4; j++) {
            int id = tid + j * 256;
            int r = id >> 3, c = id & 7;
            cp16(as + swz(r, c), xh + (size_t)(m0 + r) * E_SIZE + kbase + c * 8);
        }
#pragma unroll
        for (int j = 0; j < 4; j++) {
            int id = tid + j * 256;
            int r = id >> 3, c = id & 7;
            int gn = n0 + r;
            if (gn > V_SIZE - 1) gn = V_SIZE - 1;
            cp16(bs + swz(r, c), wh + (size_t)gn * E_SIZE + kbase + c * 8);
        }
        CP_COMMIT();
    };

    load_stage(0, 0);
    load_stage(1, 1);

    const int lrl = lane & 7;
    const int lmat = lane >> 3;

    for (int t = 0; t < KIT; t++) {
        if (t < KIT - 2) { CP_WAIT1(); } else { CP_WAIT0(); }
        __syncthreads();
        uint32_t st = sb + (t & 1) * STAGE_BYTES;
        uint32_t a_s = st, b_s = st + 16384;

#pragma unroll
        for (int kk = 0; kk < 4; kk++) {            // 4 x k16 per k-slice
            int cbase = kk * 2;
            uint32_t bfr[8][2];
#pragma unroll
            for (int pr = 0; pr < 4; pr++) {
                int r = wn + pr * 16 + lrl + (lmat >> 1) * 8;
                int c = cbase + (lmat & 1);
                uint32_t q0, q1, q2, q3;
                ldsm_x4(q0, q1, q2, q3, b_s + swz(r, c));
                bfr[pr * 2 + 0][0] = q0; bfr[pr * 2 + 0][1] = q1;
                bfr[pr * 2 + 1][0] = q2; bfr[pr * 2 + 1][1] = q3;
            }
            uint32_t afr[2][4];
#pragma unroll
            for (int mi = 0; mi < 2; mi++) {
                int r = wm + mi * 16 + lrl + (lmat & 1) * 8;
                int c = cbase + (lmat >> 1);
                ldsm_x4(afr[mi][0], afr[mi][1], afr[mi][2], afr[mi][3], a_s + swz(r, c));
            }
#pragma unroll
            for (int mi = 0; mi < 2; mi++)
#pragma unroll
                for (int ni = 0; ni < 8; ni++)
                    mma16816(acc[mi][ni], afr[mi], bfr[ni]);
        }
        __syncthreads();
        if (t + 2 < KIT) load_stage(t + 2, t & 1);
    }

    // scalar stores: V_SIZE odd -> odd rows only 4B-aligned
    const int lr = lane >> 2;
    const int lc = (lane & 3) * 2;
#pragma unroll
    for (int mi = 0; mi < 2; mi++) {
        int row0 = m0 + wm + mi * 16 + lr;
#pragma unroll
        for (int ni = 0; ni < 8; ni++) {
            int col = n0 + wn + ni * 8 + lc;
            float* d0 = C + (size_t)row0 * V_SIZE + col;
            float* d1 = C + (size_t)(row0 + 8) * V_SIZE + col;
            if (col < V_SIZE)     { d0[0] = acc[mi][ni][0]; d1[0] = acc[mi][ni][2]; }
            if (col + 1 < V_SIZE) { d0[1] = acc[mi][ni][1]; d1[1] = acc[mi][ni][3]; }
        }
    }
}

// ---------------- kernel 2: fused q+k projections (fp32 SGEMM, z selects) -----
__global__ __launch_bounds__(256, 2)
void qkproj_kernel(const float* __restrict__ A,
                   const float* __restrict__ Wq,
                   const float* __restrict__ Wk) {
    const int K = E_SIZE;
    __shared__ float As[16][128];
    __shared__ float Bs[16][128];

    const float* W = blockIdx.z ? Wk : Wq;
    float* C = blockIdx.z ? g_k : g_q;

    int tid = threadIdx.x;
    int m0 = blockIdx.y * 128;
    int n0 = blockIdx.x * 128;

    float acc[8][8];
#pragma unroll
    for (int i = 0; i < 8; i++)
#pragma unroll
        for (int j = 0; j < 8; j++) acc[i][j] = 0.f;

    int lrow = tid >> 2;
    int lk = (tid & 3) * 4;

    for (int k0 = 0; k0 < K; k0 += 16) {
#pragma unroll
        for (int l = 0; l < 2; l++) {
            int row = lrow + l * 64;
            float4 va = *(const float4*)(A + (size_t)(m0 + row) * K + k0 + lk);
            As[lk + 0][row] = va.x; As[lk + 1][row] = va.y;
            As[lk + 2][row] = va.z; As[lk + 3][row] = va.w;
            float4 vb = *(const float4*)(W + (size_t)(n0 + row) * K + k0 + lk);
            Bs[lk + 0][row] = vb.x; Bs[lk + 1][row] = vb.y;
            Bs[lk + 2][row] = vb.z; Bs[lk + 3][row] = vb.w;
        }
        __syncthreads();

        int mth = (tid >> 4) * 8;
        int nth = (tid & 15) * 8;
#pragma unroll
        for (int kk = 0; kk < 16; kk++) {
            float4 a0 = *(const float4*)&As[kk][mth];
            float4 a1 = *(const float4*)&As[kk][mth + 4];
            float4 b0 = *(const float4*)&Bs[kk][nth];
            float4 b1 = *(const float4*)&Bs[kk][nth + 4];
            float a[8] = {a0.x, a0.y, a0.z, a0.w, a1.x, a1.y, a1.z, a1.w};
            float b[8] = {b0.x, b0.y, b0.z, b0.w, b1.x, b1.y, b1.z, b1.w};
#pragma unroll
            for (int i = 0; i < 8; i++)
#pragma unroll
                for (int j = 0; j < 8; j++) acc[i][j] = fmaf(a[i], b[j], acc[i][j]);
        }
        __syncthreads();
    }

    int mrow = m0 + (tid >> 4) * 8;
    int ncol = n0 + (tid & 15) * 8;
#pragma unroll
    for (int i = 0; i < 8; i++) {
        float* crow = C + (size_t)(mrow + i) * QK_SIZE;
#pragma unroll
        for (int j = 0; j < 8; j++) crow[ncol + j] = acc[i][j];
    }
}

// ---------------- kernel 3: c = q k^T  (lower-triangle tiles only) ------------
__global__ __launch_bounds__(256, 2)
void qk_gemm_kernel() {
    int bx = blockIdx.x;
    int b = bx / 36;
    int p = bx % 36;
    int mt = 0;
    while ((mt + 1) * (mt + 2) / 2 <= p) mt++;
    int nt = p - mt * (mt + 1) / 2;

    const float* Aq = g_q + (size_t)b * T_SIZE * QK_SIZE;
    const float* Bk = g_k + (size_t)b * T_SIZE * QK_SIZE;
    float* C = g_c + (size_t)b * T_SIZE * T_SIZE;

    __shared__ float As[16][128];
    __shared__ float Bs[16][128];

    int tid = threadIdx.x;
    int m0 = mt * 128;
    int n0 = nt * 128;

    float acc[8][8];
#pragma unroll
    for (int i = 0; i < 8; i++)
#pragma unroll
        for (int j = 0; j < 8; j++) acc[i][j] = 0.f;

    int lrow = tid >> 2;
    int lk = (tid & 3) * 4;

    for (int k0 = 0; k0 < QK_SIZE; k0 += 16) {
#pragma unroll
        for (int l = 0; l < 2; l++) {
            int row = lrow + l * 64;
            float4 va = *(const float4*)(Aq + (size_t)(m0 + row) * QK_SIZE + k0 + lk);
            As[lk + 0][row] = va.x; As[lk + 1][row] = va.y;
            As[lk + 2][row] = va.z; As[lk + 3][row] = va.w;
            float4 vb = *(const float4*)(Bk + (size_t)(n0 + row) * QK_SIZE + k0 + lk);
            Bs[lk + 0][row] = vb.x; Bs[lk + 1][row] = vb.y;
            Bs[lk + 2][row] = vb.z; Bs[lk + 3][row] = vb.w;
        }
        __syncthreads();

        int mth = (tid >> 4) * 8;
        int nth = (tid & 15) * 8;
#pragma unroll
        for (int kk = 0; kk < 16; kk++) {
            float4 a0 = *(const float4*)&As[kk][mth];
            float4 a1 = *(const float4*)&As[kk][mth + 4];
            float4 b0 = *(const float4*)&Bs[kk][nth];
            float4 b1 = *(const float4*)&Bs[kk][nth + 4];
            float a[8] = {a0.x, a0.y, a0.z, a0.w, a1.x, a1.y, a1.z, a1.w};
            float b[8] = {b0.x, b0.y, b0.z, b0.w, b1.x, b1.y, b1.z, b1.w};
#pragma unroll
            for (int i = 0; i < 8; i++)
#pragma unroll
                for (int j = 0; j < 8; j++) acc[i][j] = fmaf(a[i], b[j], acc[i][j]);
        }
        __syncthreads();
    }

    int mrow = m0 + (tid >> 4) * 8;
    int ncol = n0 + (tid & 15) * 8;
#pragma unroll
    for (int i = 0; i < 8; i++) {
        float* crow = C + (size_t)(mrow + i) * T_SIZE;
#pragma unroll
        for (int j = 0; j < 8; j++) crow[ncol + j] = acc[i][j];
    }
}

// ---------------- kernel 4: scatter-add  logits[r, idx[b,s]] += c[r,s]/QK -----
__global__ void scatter_kernel(const int* __restrict__ idx,
                               float* __restrict__ logits) {
    int r = blockIdx.x;
    int b = r >> 10;
    int t = r & 1023;

    const float* crow = g_c + (size_t)b * T_SIZE * T_SIZE + (size_t)t * T_SIZE;
    const int* ib = idx + b * T_SIZE;
    float* lrow = logits + (size_t)r * V_SIZE;

    for (int s = threadIdx.x; s <= t; s += blockDim.x)
        atomicAdd(&lrow[ib[s]], crow[s] * (1.0f / QK_SIZE));
}

// ---------------- launch ----------------
extern "C" void kernel_launch(void* const* d_in, const int* in_sizes, int n_in,
                              void* d_out, int out_size) {
    const int*   idx    = (const int*)d_in[0];
    const float* emb_w  = (const float*)d_in[1];
    const float* ln_g   = (const float*)d_in[2];
    const float* ln_b   = (const float*)d_in[3];
    const float* head_w = (const float*)d_in[4];
    const float* head_q = (const float*)d_in[5];
    const float* head_k = (const float*)d_in[6];

    void *px, *pxh, *pwh;
    cudaGetSymbolAddress(&px, g_x);
    cudaGetSymbolAddress(&pxh, g_xh);
    cudaGetSymbolAddress(&pwh, g_wh);

    float* out    = (float*)d_out;
    float* logits = out;

    const size_t logits_elems = (size_t)M_ROWS * V_SIZE;
    const size_t x_elems      = (size_t)M_ROWS * E_SIZE;
    float* xout = nullptr;
    if ((size_t)out_size >= logits_elems + x_elems)
        xout = out + ((size_t)out_size - x_elems);

    // 1) x = layernorm(emb[idx]) (+ fp16 copy of x)
    ln_kernel<<<M_ROWS, 256>>>(idx, emb_w, ln_g, ln_b, xout);

    // 1b) head_w -> fp16
    {
        size_t n2 = (size_t)V_SIZE * E_SIZE / 2;
        wsplit_kernel<<<(unsigned)((n2 + 255) / 256), 256>>>(head_w);
    }

    // 2) fused q+k projections
    {
        dim3 grid(QK_SIZE / 128, M_ROWS / 128, 2);
        qkproj_kernel<<<grid, 256>>>((float*)px, head_q, head_k);
    }

    // 3) c = q k^T lower-triangle tiles into g_c
    qk_gemm_kernel<<<B_SIZE * 36, 256>>>();

    // 4) logits = x @ head_w^T via single-pass fp16 mma.sync
    {
        cudaFuncSetAttribute(mma_gemm_kernel, cudaFuncAttributeMaxDynamicSharedMemorySize, SMEM_DYN);
        dim3 grid(M_ROWS / BM, (V_SIZE + BN - 1) / BN);
        mma_gemm_kernel<<<grid, 256, SMEM_DYN>>>(
            (const __half*)pxh, (const __half*)pwh, logits);
    }

    // 5) causal copy-scatter from precomputed c
    scatter_kernel<<<M_ROWS, 256>>>(idx, logits);
}

// round 13
// speedup vs baseline: 2.2459x; 1.1063x over previous
#include <cuda_runtime.h>
#include <cuda_bf16.h>
#include <cuda_fp16.h>
#include <cstdint>

#define V_SIZE 50257
#define E_SIZE 768
#define QK_SIZE 256
#define B_SIZE 4
#define T_SIZE 1024
#define M_ROWS (B_SIZE * T_SIZE)   // 4096
#define LN_EPS 1e-5f

#define BM 128
#define BN 128
#define BK 64                          // 64 fp16 = 128B rows (xor-swizzled)
#define KIT (E_SIZE / BK)              // 12 k-slices (vocab GEMM)
#define KIT_QK (QK_SIZE / BK)          // 4 k-slices (qk^T GEMM)
#define STAGE_BYTES 32768              // A 16K | B 16K
#define SMEM_DYN (2 * STAGE_BYTES)

// ---------------- scratch (static device memory; no allocation) ----------------
__device__ __align__(256) float g_x[M_ROWS * E_SIZE];
__device__ __align__(256) __half g_xh[M_ROWS * E_SIZE];
__device__ __align__(256) __half g_wh[(size_t)V_SIZE * E_SIZE];
__device__ __align__(256) __half g_wqh[QK_SIZE * E_SIZE];
__device__ __align__(256) __half g_wkh[QK_SIZE * E_SIZE];
__device__ __align__(256) __half g_qh[M_ROWS * QK_SIZE];
__device__ __align__(256) __half g_kh[M_ROWS * QK_SIZE];

// ---------------- PTX helpers (generic PTX only — no sm_103a features) --------
__device__ __forceinline__ uint32_t smem_u32(const void* p) {
    uint32_t a;
    asm("{ .reg .u64 t; cvta.to.shared.u64 t, %1; cvt.u32.u64 %0, t; }" : "=r"(a) : "l"(p));
    return a;
}
__device__ __forceinline__ void cp16(uint32_t dst, const void* src) {
    asm volatile("cp.async.cg.shared.global [%0], [%1], 16;" :: "r"(dst), "l"(src));
}
#define CP_COMMIT() asm volatile("cp.async.commit_group;" ::: "memory")
#define CP_WAIT1()  asm volatile("cp.async.wait_group 1;" ::: "memory")
#define CP_WAIT0()  asm volatile("cp.async.wait_group 0;" ::: "memory")

__device__ __forceinline__ void ldsm_x4(uint32_t& r0, uint32_t& r1, uint32_t& r2, uint32_t& r3,
                                        uint32_t addr) {
    asm volatile("ldmatrix.sync.aligned.m8n8.x4.shared.b16 {%0,%1,%2,%3}, [%4];"
                 : "=r"(r0), "=r"(r1), "=r"(r2), "=r"(r3) : "r"(addr));
}
__device__ __forceinline__ void mma16816(float* d, const uint32_t* a, const uint32_t* b) {
    asm volatile("mma.sync.aligned.m16n8k16.row.col.f32.f16.f16.f32 "
                 "{%0,%1,%2,%3}, {%4,%5,%6,%7}, {%8,%9}, {%0,%1,%2,%3};"
                 : "+f"(d[0]), "+f"(d[1]), "+f"(d[2]), "+f"(d[3])
                 : "r"(a[0]), "r"(a[1]), "r"(a[2]), "r"(a[3]), "r"(b[0]), "r"(b[1]));
}
__device__ __forceinline__ uint32_t swz(int r, int c) {
    return (uint32_t)(r * 128 + ((c ^ (r & 7)) << 4));
}

// ---------------- kernel 0: gather + layernorm (+ fp16 copy of x) -------------
__global__ void ln_kernel(const int* __restrict__ idx,
                          const float* __restrict__ emb,
                          const float* __restrict__ gamma,
                          const float* __restrict__ beta,
                          float* __restrict__ xout) {
    int r = blockIdx.x;
    int tok = idx[r];
    const float* e = emb + (size_t)tok * E_SIZE;
    int tid = threadIdx.x;

    float v[3];
    float s = 0.f;
#pragma unroll
    for (int j = 0; j < 3; j++) { v[j] = e[tid + j * 256]; s += v[j]; }

    __shared__ float red[8];
    __shared__ float sh_mu, sh_inv;
#pragma unroll
    for (int o = 16; o > 0; o >>= 1) s += __shfl_xor_sync(0xffffffffu, s, o);
    if ((tid & 31) == 0) red[tid >> 5] = s;
    __syncthreads();
    if (tid == 0) {
        float tot = 0.f;
#pragma unroll
        for (int w = 0; w < 8; w++) tot += red[w];
        sh_mu = tot * (1.f / E_SIZE);
    }
    __syncthreads();
    float mu = sh_mu;

    float s2 = 0.f;
#pragma unroll
    for (int j = 0; j < 3; j++) { float d = v[j] - mu; s2 += d * d; }
#pragma unroll
    for (int o = 16; o > 0; o >>= 1) s2 += __shfl_xor_sync(0xffffffffu, s2, o);
    if ((tid & 31) == 0) red[tid >> 5] = s2;
    __syncthreads();
    if (tid == 0) {
        float tot = 0.f;
#pragma unroll
        for (int w = 0; w < 8; w++) tot += red[w];
        sh_inv = rsqrtf(tot * (1.f / E_SIZE) + LN_EPS);
    }
    __syncthreads();
    float inv = sh_inv;

#pragma unroll
    for (int j = 0; j < 3; j++) {
        int i = tid + j * 256;
        float y = (v[j] - mu) * inv * gamma[i] + beta[i];
        size_t o = (size_t)r * E_SIZE + i;
        g_x[o] = y;
        g_xh[o] = __float2half_rn(y);
        if (xout) xout[o] = y;
    }
}

// ---------------- kernel 0b: head_w -> fp16 ----------------
__global__ void wsplit_kernel(const float* __restrict__ w) {
    size_t i2 = (size_t)blockIdx.x * blockDim.x + threadIdx.x;
    size_t n2 = (size_t)V_SIZE * E_SIZE / 2;
    if (i2 >= n2) return;
    float2 v = ((const float2*)w)[i2];
    ((__half2*)g_wh)[i2] = __floats2half2_rn(v.x, v.y);
}

// ---------------- kernel 0c: head_q / head_k -> fp16 ----------------
__global__ void wqk_kernel(const float* __restrict__ wq, const float* __restrict__ wk) {
    int i2 = blockIdx.x * blockDim.x + threadIdx.x;
    int n2 = QK_SIZE * E_SIZE / 2;
    if (i2 >= n2) return;
    float2 a = ((const float2*)wq)[i2];
    float2 b = ((const float2*)wk)[i2];
    ((__half2*)g_wqh)[i2] = __floats2half2_rn(a.x, a.y);
    ((__half2*)g_wkh)[i2] = __floats2half2_rn(b.x, b.y);
}

// ---------------- kernel 1: fp16 mma.sync vocab GEMM (single pass) ------------
__global__ __launch_bounds__(256)
void mma_gemm_kernel(const __half* __restrict__ xh,
                     const __half* __restrict__ wh,
                     float* __restrict__ C) {
    extern __shared__ char smem[];
    const uint32_t sb = smem_u32(smem);

    const int tid = threadIdx.x;
    const int wid = tid >> 5;
    const int lane = tid & 31;
    const int m0 = blockIdx.x * BM;
    const int n0 = blockIdx.y * BN;

    const int wm = (wid & 3) * 32;
    const int wn = (wid >> 2) * 64;

    float acc[2][8][4];
#pragma unroll
    for (int mi = 0; mi < 2; mi++)
#pragma unroll
        for (int ni = 0; ni < 8; ni++)
#pragma unroll
            for (int q = 0; q < 4; q++) acc[mi][ni][q] = 0.f;

    auto load_stage = [&](int kit, int slot) {
        int kbase = kit * BK;
        uint32_t st = sb + slot * STAGE_BYTES;
        uint32_t as = st, bs = st + 16384;
#pragma unroll
        for (int j = 0; j < 4; j++) {
            int id = tid + j * 256;
            int r = id >> 3, c = id & 7;
            cp16(as + swz(r, c), xh + (size_t)(m0 + r) * E_SIZE + kbase + c * 8);
        }
#pragma unroll
        for (int j = 0; j < 4; j++) {
            int id = tid + j * 256;
            int r = id >> 3, c = id & 7;
            int gn = n0 + r;
            if (gn > V_SIZE - 1) gn = V_SIZE - 1;
            cp16(bs + swz(r, c), wh + (size_t)gn * E_SIZE + kbase + c * 8);
        }
        CP_COMMIT();
    };

    load_stage(0, 0);
    load_stage(1, 1);

    const int lrl = lane & 7;
    const int lmat = lane >> 3;

    for (int t = 0; t < KIT; t++) {
        if (t < KIT - 2) { CP_WAIT1(); } else { CP_WAIT0(); }
        __syncthreads();
        uint32_t st = sb + (t & 1) * STAGE_BYTES;
        uint32_t a_s = st, b_s = st + 16384;

#pragma unroll
        for (int kk = 0; kk < 4; kk++) {
            int cbase = kk * 2;
            uint32_t bfr[8][2];
#pragma unroll
            for (int pr = 0; pr < 4; pr++) {
                int r = wn + pr * 16 + lrl + (lmat >> 1) * 8;
                int c = cbase + (lmat & 1);
                uint32_t q0, q1, q2, q3;
                ldsm_x4(q0, q1, q2, q3, b_s + swz(r, c));
                bfr[pr * 2 + 0][0] = q0; bfr[pr * 2 + 0][1] = q1;
                bfr[pr * 2 + 1][0] = q2; bfr[pr * 2 + 1][1] = q3;
            }
            uint32_t afr[2][4];
#pragma unroll
            for (int mi = 0; mi < 2; mi++) {
                int r = wm + mi * 16 + lrl + (lmat & 1) * 8;
                int c = cbase + (lmat >> 1);
                ldsm_x4(afr[mi][0], afr[mi][1], afr[mi][2], afr[mi][3], a_s + swz(r, c));
            }
#pragma unroll
            for (int mi = 0; mi < 2; mi++)
#pragma unroll
                for (int ni = 0; ni < 8; ni++)
                    mma16816(acc[mi][ni], afr[mi], bfr[ni]);
        }
        __syncthreads();
        if (t + 2 < KIT) load_stage(t + 2, t & 1);
    }

    // scalar stores: V_SIZE odd -> odd rows only 4B-aligned
    const int lr = lane >> 2;
    const int lc = (lane & 3) * 2;
#pragma unroll
    for (int mi = 0; mi < 2; mi++) {
        int row0 = m0 + wm + mi * 16 + lr;
#pragma unroll
        for (int ni = 0; ni < 8; ni++) {
            int col = n0 + wn + ni * 8 + lc;
            float* d0 = C + (size_t)row0 * V_SIZE + col;
            float* d1 = C + (size_t)(row0 + 8) * V_SIZE + col;
            if (col < V_SIZE)     { d0[0] = acc[mi][ni][0]; d1[0] = acc[mi][ni][2]; }
            if (col + 1 < V_SIZE) { d0[1] = acc[mi][ni][1]; d1[1] = acc[mi][ni][3]; }
        }
    }
}

// ---------------- kernel 2: fp16 q+k projections (mma.sync, z selects) --------
// q/k[4096, 256] = xh @ W^T, output fp16
__global__ __launch_bounds__(256)
void qkproj_kernel(const __half* __restrict__ xh) {
    extern __shared__ char smem[];
    const uint32_t sb = smem_u32(smem);

    const __half* W = blockIdx.z ? g_wkh : g_wqh;
    __half* O = blockIdx.z ? g_kh : g_qh;

    const int tid = threadIdx.x;
    const int wid = tid >> 5;
    const int lane = tid & 31;
    const int m0 = blockIdx.x * BM;
    const int n0 = blockIdx.y * BN;     // 0 or 128

    const int wm = (wid & 3) * 32;
    const int wn = (wid >> 2) * 64;

    float acc[2][8][4];
#pragma unroll
    for (int mi = 0; mi < 2; mi++)
#pragma unroll
        for (int ni = 0; ni < 8; ni++)
#pragma unroll
            for (int q = 0; q < 4; q++) acc[mi][ni][q] = 0.f;

    auto load_stage = [&](int kit, int slot) {
        int kbase = kit * BK;
        uint32_t st = sb + slot * STAGE_BYTES;
        uint32_t as = st, bs = st + 16384;
#pragma unroll
        for (int j = 0; j < 4; j++) {
            int id = tid + j * 256;
            int r = id >> 3, c = id & 7;
            cp16(as + swz(r, c), xh + (size_t)(m0 + r) * E_SIZE + kbase + c * 8);
        }
#pragma unroll
        for (int j = 0; j < 4; j++) {
            int id = tid + j * 256;
            int r = id >> 3, c = id & 7;
            cp16(bs + swz(r, c), W + (size_t)(n0 + r) * E_SIZE + kbase + c * 8);
        }
        CP_COMMIT();
    };

    load_stage(0, 0);
    load_stage(1, 1);

    const int lrl = lane & 7;
    const int lmat = lane >> 3;

    for (int t = 0; t < KIT; t++) {
        if (t < KIT - 2) { CP_WAIT1(); } else { CP_WAIT0(); }
        __syncthreads();
        uint32_t st = sb + (t & 1) * STAGE_BYTES;
        uint32_t a_s = st, b_s = st + 16384;

#pragma unroll
        for (int kk = 0; kk < 4; kk++) {
            int cbase = kk * 2;
            uint32_t bfr[8][2];
#pragma unroll
            for (int pr = 0; pr < 4; pr++) {
                int r = wn + pr * 16 + lrl + (lmat >> 1) * 8;
                int c = cbase + (lmat & 1);
                uint32_t q0, q1, q2, q3;
                ldsm_x4(q0, q1, q2, q3, b_s + swz(r, c));
                bfr[pr * 2 + 0][0] = q0; bfr[pr * 2 + 0][1] = q1;
                bfr[pr * 2 + 1][0] = q2; bfr[pr * 2 + 1][1] = q3;
            }
            uint32_t afr[2][4];
#pragma unroll
            for (int mi = 0; mi < 2; mi++) {
                int r = wm + mi * 16 + lrl + (lmat & 1) * 8;
                int c = cbase + (lmat >> 1);
                ldsm_x4(afr[mi][0], afr[mi][1], afr[mi][2], afr[mi][3], a_s + swz(r, c));
            }
#pragma unroll
            for (int mi = 0; mi < 2; mi++)
#pragma unroll
                for (int ni = 0; ni < 8; ni++)
                    mma16816(acc[mi][ni], afr[mi], bfr[ni]);
        }
        __syncthreads();
        if (t + 2 < KIT) load_stage(t + 2, t & 1);
    }

    // fp16 stores (row stride 256 halfs = 512B aligned; col even -> 4B aligned)
    const int lr = lane >> 2;
    const int lc = (lane & 3) * 2;
#pragma unroll
    for (int mi = 0; mi < 2; mi++) {
        int row0 = m0 + wm + mi * 16 + lr;
#pragma unroll
        for (int ni = 0; ni < 8; ni++) {
            int col = n0 + wn + ni * 8 + lc;
            *(__half2*)(O + (size_t)row0 * QK_SIZE + col) =
                __floats2half2_rn(acc[mi][ni][0], acc[mi][ni][1]);
            *(__half2*)(O + (size_t)(row0 + 8) * QK_SIZE + col) =
                __floats2half2_rn(acc[mi][ni][2], acc[mi][ni][3]);
        }
    }
}

// ---------------- kernel 3: fused c = q k^T / QK + scatter-add into logits ----
// lower-triangle 128x128 tiles; fp16 mma over K=256; atomicAdd epilogue
__global__ __launch_bounds__(256)
void qk_scatter_kernel(const int* __restrict__ idx, float* __restrict__ logits) {
    extern __shared__ char smem[];
    const uint32_t sb = smem_u32(smem);
    __shared__ int ibs[128];

    int bx = blockIdx.x;
    int b = bx / 36;
    int p = bx % 36;
    int mt = 0;
    while ((mt + 1) * (mt + 2) / 2 <= p) mt++;
    int nt = p - mt * (mt + 1) / 2;

    const int tid = threadIdx.x;
    const int wid = tid >> 5;
    const int lane = tid & 31;
    const int m0 = b * T_SIZE + mt * 128;   // global row into g_qh
    const int n0 = b * T_SIZE + nt * 128;   // global row into g_kh

    if (tid < 128) ibs[tid] = idx[n0 + tid];

    const int wm = (wid & 3) * 32;
    const int wn = (wid >> 2) * 64;

    float acc[2][8][4];
#pragma unroll
    for (int mi = 0; mi < 2; mi++)
#pragma unroll
        for (int ni = 0; ni < 8; ni++)
#pragma unroll
            for (int q = 0; q < 4; q++) acc[mi][ni][q] = 0.f;

    auto load_stage = [&](int kit, int slot) {
        int kbase = kit * BK;
        uint32_t st = sb + slot * STAGE_BYTES;
        uint32_t as = st, bs = st + 16384;
#pragma unroll
        for (int j = 0; j < 4; j++) {
            int id = tid + j * 256;
            int r = id >> 3, c = id & 7;
            cp16(as + swz(r, c), g_qh + (size_t)(m0 + r) * QK_SIZE + kbase + c * 8);
        }
#pragma unroll
        for (int j = 0; j < 4; j++) {
            int id = tid + j * 256;
            int r = id >> 3, c = id & 7;
            cp16(bs + swz(r, c), g_kh + (size_t)(n0 + r) * QK_SIZE + kbase + c * 8);
        }
        CP_COMMIT();
    };

    load_stage(0, 0);
    load_stage(1, 1);

    const int lrl = lane & 7;
    const int lmat = lane >> 3;

    for (int t = 0; t < KIT_QK; t++) {
        if (t < KIT_QK - 2) { CP_WAIT1(); } else { CP_WAIT0(); }
        __syncthreads();
        uint32_t st = sb + (t & 1) * STAGE_BYTES;
        uint32_t a_s = st, b_s = st + 16384;

#pragma unroll
        for (int kk = 0; kk < 4; kk++) {
            int cbase = kk * 2;
            uint32_t bfr[8][2];
#pragma unroll
            for (int pr = 0; pr < 4; pr++) {
                int r = wn + pr * 16 + lrl + (lmat >> 1) * 8;
                int c = cbase + (lmat & 1);
                uint32_t q0, q1, q2, q3;
                ldsm_x4(q0, q1, q2, q3, b_s + swz(r, c));
                bfr[pr * 2 + 0][0] = q0; bfr[pr * 2 + 0][1] = q1;
                bfr[pr * 2 + 1][0] = q2; bfr[pr * 2 + 1][1] = q3;
            }
            uint32_t afr[2][4];
#pragma unroll
            for (int mi = 0; mi < 2; mi++) {
                int r = wm + mi * 16 + lrl + (lmat & 1) * 8;
                int c = cbase + (lmat >> 1);
                ldsm_x4(afr[mi][0], afr[mi][1], afr[mi][2], afr[mi][3], a_s + swz(r, c));
            }
#pragma unroll
            for (int mi = 0; mi < 2; mi++)
#pragma unroll
                for (int ni = 0; ni < 8; ni++)
                    mma16816(acc[mi][ni], afr[mi], bfr[ni]);
        }
        __syncthreads();
        if (t + 2 < KIT_QK) load_stage(t + 2, t & 1);
    }

    // atomic epilogue: logits[b*T + tloc, idx[b*T + sloc]] += c/QK for sloc<=tloc
    const int lr = lane >> 2;
    const int lc = (lane & 3) * 2;
    const float sc = 1.0f / QK_SIZE;
#pragma unroll
    for (int mi = 0; mi < 2; mi++) {
        int tl0 = mt * 128 + wm + mi * 16 + lr;     // local t (row), and tl0+8
#pragma unroll
        for (int ni = 0; ni < 8; ni++) {
            int cl = wn + ni * 8 + lc;              // local col 0..127
            int sl = nt * 128 + cl;                  // local s
            float* l0 = logits + (size_t)(b * T_SIZE + tl0) * V_SIZE;
            float* l1 = logits + (size_t)(b * T_SIZE + tl0 + 8) * V_SIZE;
            int v0 = ibs[cl], v1 = ibs[cl + 1];
            if (sl <= tl0)         atomicAdd(l0 + v0, acc[mi][ni][0] * sc);
            if (sl + 1 <= tl0)     atomicAdd(l0 + v1, acc[mi][ni][1] * sc);
            if (sl <= tl0 + 8)     atomicAdd(l1 + v0, acc[mi][ni][2] * sc);
            if (sl + 1 <= tl0 + 8) atomicAdd(l1 + v1, acc[mi][ni][3] * sc);
        }
    }
}

// ---------------- launch ----------------
extern "C" void kernel_launch(void* const* d_in, const int* in_sizes, int n_in,
                              void* d_out, int out_size) {
    const int*   idx    = (const int*)d_in[0];
    const float* emb_w  = (const float*)d_in[1];
    const float* ln_g   = (const float*)d_in[2];
    const float* ln_b   = (const float*)d_in[3];
    const float* head_w = (const float*)d_in[4];
    const float* head_q = (const float*)d_in[5];
    const float* head_k = (const float*)d_in[6];

    void *pxh, *pwh;
    cudaGetSymbolAddress(&pxh, g_xh);
    cudaGetSymbolAddress(&pwh, g_wh);

    float* out    = (float*)d_out;
    float* logits = out;

    const size_t logits_elems = (size_t)M_ROWS * V_SIZE;
    const size_t x_elems      = (size_t)M_ROWS * E_SIZE;
    float* xout = nullptr;
    if ((size_t)out_size >= logits_elems + x_elems)
        xout = out + ((size_t)out_size - x_elems);

    // 1) x = layernorm(emb[idx]) (+ fp16 copy of x)
    ln_kernel<<<M_ROWS, 256>>>(idx, emb_w, ln_g, ln_b, xout);

    // 1b) head_w -> fp16 ; head_q/head_k -> fp16
    {
        size_t n2 = (size_t)V_SIZE * E_SIZE / 2;
        wsplit_kernel<<<(unsigned)((n2 + 255) / 256), 256>>>(head_w);
        int m2 = QK_SIZE * E_SIZE / 2;
        wqk_kernel<<<(m2 + 255) / 256, 256>>>(head_q, head_k);
    }

    // 2) q,k projections via fp16 mma.sync (outputs fp16)
    {
        cudaFuncSetAttribute(qkproj_kernel, cudaFuncAttributeMaxDynamicSharedMemorySize, SMEM_DYN);
        dim3 grid(M_ROWS / BM, QK_SIZE / BN, 2);
        qkproj_kernel<<<grid, 256, SMEM_DYN>>>((const __half*)pxh);
    }

    // 3) logits = x @ head_w^T via single-pass fp16 mma.sync
    {
        cudaFuncSetAttribute(mma_gemm_kernel, cudaFuncAttributeMaxDynamicSharedMemorySize, SMEM_DYN);
        dim3 grid(M_ROWS / BM, (V_SIZE + BN - 1) / BN);
        mma_gemm_kernel<<<grid, 256, SMEM_DYN>>>(
            (const __half*)pxh, (const __half*)pwh, logits);
    }

    // 4) fused causal qk^T + copy-scatter into logits (after logits exist)
    {
        cudaFuncSetAttribute(qk_scatter_kernel, cudaFuncAttributeMaxDynamicSharedMemorySize, SMEM_DYN);
        qk_scatter_kernel<<<B_SIZE * 36, 256, SMEM_DYN>>>(idx, logits);
    }
}

// round 14
// speedup vs baseline: 2.6806x; 1.1936x over previous
#include <cuda_runtime.h>
#include <cuda_bf16.h>
#include <cuda_fp16.h>
#include <cstdint>

#define V_SIZE 50257
#define E_SIZE 768
#define QK_SIZE 256
#define B_SIZE 4
#define T_SIZE 1024
#define M_ROWS (B_SIZE * T_SIZE)   // 4096
#define LN_EPS 1e-5f

#define BM 128
#define BN 128
#define BK 64                          // 64 fp16 = 128B rows (xor-swizzled)
#define KIT (E_SIZE / BK)              // 12 k-slices (vocab GEMM)
#define KIT_QK (QK_SIZE / BK)          // 4 k-slices (qk^T GEMM)
#define STAGE_BYTES 32768              // A 16K | B 16K
#define STG_STRIDE 132                 // fp32 epilogue staging stride
#define SMEM_DYN (128 * STG_STRIDE * 4)  // 67584 > 2*STAGE_BYTES, covers both uses

// ---------------- scratch (static device memory; no allocation) ----------------
__device__ __align__(256) __half g_xh[M_ROWS * E_SIZE];
__device__ __align__(256) __half g_wh[(size_t)V_SIZE * E_SIZE];
__device__ __align__(256) __half g_wqh[QK_SIZE * E_SIZE];
__device__ __align__(256) __half g_wkh[QK_SIZE * E_SIZE];
__device__ __align__(256) __half g_qh[M_ROWS * QK_SIZE];
__device__ __align__(256) __half g_kh[M_ROWS * QK_SIZE];

// ---------------- PTX helpers (generic PTX only — no sm_103a features) --------
__device__ __forceinline__ uint32_t smem_u32(const void* p) {
    uint32_t a;
    asm("{ .reg .u64 t; cvta.to.shared.u64 t, %1; cvt.u32.u64 %0, t; }" : "=r"(a) : "l"(p));
    return a;
}
__device__ __forceinline__ void cp16(uint32_t dst, const void* src) {
    asm volatile("cp.async.cg.shared.global [%0], [%1], 16;" :: "r"(dst), "l"(src));
}
#define CP_COMMIT() asm volatile("cp.async.commit_group;" ::: "memory")
#define CP_WAIT1()  asm volatile("cp.async.wait_group 1;" ::: "memory")
#define CP_WAIT0()  asm volatile("cp.async.wait_group 0;" ::: "memory")

__device__ __forceinline__ void ldsm_x4(uint32_t& r0, uint32_t& r1, uint32_t& r2, uint32_t& r3,
                                        uint32_t addr) {
    asm volatile("ldmatrix.sync.aligned.m8n8.x4.shared.b16 {%0,%1,%2,%3}, [%4];"
                 : "=r"(r0), "=r"(r1), "=r"(r2), "=r"(r3) : "r"(addr));
}
__device__ __forceinline__ void mma16816(float* d, const uint32_t* a, const uint32_t* b) {
    asm volatile("mma.sync.aligned.m16n8k16.row.col.f32.f16.f16.f32 "
                 "{%0,%1,%2,%3}, {%4,%5,%6,%7}, {%8,%9}, {%0,%1,%2,%3};"
                 : "+f"(d[0]), "+f"(d[1]), "+f"(d[2]), "+f"(d[3])
                 : "r"(a[0]), "r"(a[1]), "r"(a[2]), "r"(a[3]), "r"(b[0]), "r"(b[1]));
}
__device__ __forceinline__ uint32_t swz(int r, int c) {
    return (uint32_t)(r * 128 + ((c ^ (r & 7)) << 4));
}

// ---------------- kernel 0: gather + layernorm (fp16 x + fp32 xout) -----------
__global__ void ln_kernel(const int* __restrict__ idx,
                          const float* __restrict__ emb,
                          const float* __restrict__ gamma,
                          const float* __restrict__ beta,
                          float* __restrict__ xout) {
    int r = blockIdx.x;
    int tok = idx[r];
    const float* e = emb + (size_t)tok * E_SIZE;
    int tid = threadIdx.x;

    float v[3];
    float s = 0.f;
#pragma unroll
    for (int j = 0; j < 3; j++) { v[j] = e[tid + j * 256]; s += v[j]; }

    __shared__ float red[8];
    __shared__ float sh_mu, sh_inv;
#pragma unroll
    for (int o = 16; o > 0; o >>= 1) s += __shfl_xor_sync(0xffffffffu, s, o);
    if ((tid & 31) == 0) red[tid >> 5] = s;
    __syncthreads();
    if (tid == 0) {
        float tot = 0.f;
#pragma unroll
        for (int w = 0; w < 8; w++) tot += red[w];
        sh_mu = tot * (1.f / E_SIZE);
    }
    __syncthreads();
    float mu = sh_mu;

    float s2 = 0.f;
#pragma unroll
    for (int j = 0; j < 3; j++) { float d = v[j] - mu; s2 += d * d; }
#pragma unroll
    for (int o = 16; o > 0; o >>= 1) s2 += __shfl_xor_sync(0xffffffffu, s2, o);
    if ((tid & 31) == 0) red[tid >> 5] = s2;
    __syncthreads();
    if (tid == 0) {
        float tot = 0.f;
#pragma unroll
        for (int w = 0; w < 8; w++) tot += red[w];
        sh_inv = rsqrtf(tot * (1.f / E_SIZE) + LN_EPS);
    }
    __syncthreads();
    float inv = sh_inv;

#pragma unroll
    for (int j = 0; j < 3; j++) {
        int i = tid + j * 256;
        float y = (v[j] - mu) * inv * gamma[i] + beta[i];
        size_t o = (size_t)r * E_SIZE + i;
        g_xh[o] = __float2half_rn(y);
        if (xout) xout[o] = y;
    }
}

// ---------------- kernel 0b: head_w -> fp16 ----------------
__global__ void wsplit_kernel(const float* __restrict__ w) {
    size_t i2 = (size_t)blockIdx.x * blockDim.x + threadIdx.x;
    size_t n2 = (size_t)V_SIZE * E_SIZE / 2;
    if (i2 >= n2) return;
    float2 v = ((const float2*)w)[i2];
    ((__half2*)g_wh)[i2] = __floats2half2_rn(v.x, v.y);
}

// ---------------- kernel 0c: head_q / head_k -> fp16 ----------------
__global__ void wqk_kernel(const float* __restrict__ wq, const float* __restrict__ wk) {
    int i2 = blockIdx.x * blockDim.x + threadIdx.x;
    int n2 = QK_SIZE * E_SIZE / 2;
    if (i2 >= n2) return;
    float2 a = ((const float2*)wq)[i2];
    float2 b = ((const float2*)wk)[i2];
    ((__half2*)g_wqh)[i2] = __floats2half2_rn(a.x, a.y);
    ((__half2*)g_wkh)[i2] = __floats2half2_rn(b.x, b.y);
}

// ---------------- kernel 1: fp16 mma.sync vocab GEMM (single pass) ------------
// Epilogue stages the fp32 tile in SMEM (reusing pipeline buffers) so global
// stores are consecutive-lane coalesced (old fragment-order scalar stores had
// 2x DRAM write amplification: 8 rows x 1 sector per warp store).
__global__ __launch_bounds__(256)
void mma_gemm_kernel(const __half* __restrict__ xh,
                     const __half* __restrict__ wh,
                     float* __restrict__ C) {
    extern __shared__ char smem[];
    const uint32_t sb = smem_u32(smem);

    const int tid = threadIdx.x;
    const int wid = tid >> 5;
    const int lane = tid & 31;
    const int m0 = blockIdx.x * BM;
    const int n0 = blockIdx.y * BN;

    const int wm = (wid & 3) * 32;
    const int wn = (wid >> 2) * 64;

    float acc[2][8][4];
#pragma unroll
    for (int mi = 0; mi < 2; mi++)
#pragma unroll
        for (int ni = 0; ni < 8; ni++)
#pragma unroll
            for (int q = 0; q < 4; q++) acc[mi][ni][q] = 0.f;

    auto load_stage = [&](int kit, int slot) {
        int kbase = kit * BK;
        uint32_t st = sb + slot * STAGE_BYTES;
        uint32_t as = st, bs = st + 16384;
#pragma unroll
        for (int j = 0; j < 4; j++) {
            int id = tid + j * 256;
            int r = id >> 3, c = id & 7;
            cp16(as + swz(r, c), xh + (size_t)(m0 + r) * E_SIZE + kbase + c * 8);
        }
#pragma unroll
        for (int j = 0; j < 4; j++) {
            int id = tid + j * 256;
            int r = id >> 3, c = id & 7;
            int gn = n0 + r;
            if (gn > V_SIZE - 1) gn = V_SIZE - 1;
            cp16(bs + swz(r, c), wh + (size_t)gn * E_SIZE + kbase + c * 8);
        }
        CP_COMMIT();
    };

    load_stage(0, 0);
    load_stage(1, 1);

    const int lrl = lane & 7;
    const int lmat = lane >> 3;

    for (int t = 0; t < KIT; t++) {
        if (t < KIT - 2) { CP_WAIT1(); } else { CP_WAIT0(); }
        __syncthreads();
        uint32_t st = sb + (t & 1) * STAGE_BYTES;
        uint32_t a_s = st, b_s = st + 16384;

#pragma unroll
        for (int kk = 0; kk < 4; kk++) {
            int cbase = kk * 2;
            uint32_t bfr[8][2];
#pragma unroll
            for (int pr = 0; pr < 4; pr++) {
                int r = wn + pr * 16 + lrl + (lmat >> 1) * 8;
                int c = cbase + (lmat & 1);
                uint32_t q0, q1, q2, q3;
                ldsm_x4(q0, q1, q2, q3, b_s + swz(r, c));
                bfr[pr * 2 + 0][0] = q0; bfr[pr * 2 + 0][1] = q1;
                bfr[pr * 2 + 1][0] = q2; bfr[pr * 2 + 1][1] = q3;
            }
            uint32_t afr[2][4];
#pragma unroll
            for (int mi = 0; mi < 2; mi++) {
                int r = wm + mi * 16 + lrl + (lmat & 1) * 8;
                int c = cbase + (lmat >> 1);
                ldsm_x4(afr[mi][0], afr[mi][1], afr[mi][2], afr[mi][3], a_s + swz(r, c));
            }
#pragma unroll
            for (int mi = 0; mi < 2; mi++)
#pragma unroll
                for (int ni = 0; ni < 8; ni++)
                    mma16816(acc[mi][ni], afr[mi], bfr[ni]);
        }
        __syncthreads();
        if (t + 2 < KIT) load_stage(t + 2, t & 1);
    }

    // ---- staged epilogue: fragments -> SMEM -> coalesced global stores ----
    __syncthreads();                       // pipeline buffers now reusable
    float* stg = (float*)smem;             // 128 x STG_STRIDE fp32
    const int lr = lane >> 2;
    const int lc = (lane & 3) * 2;
#pragma unroll
    for (int mi = 0; mi < 2; mi++) {
        int r0 = wm + mi * 16 + lr;
#pragma unroll
        for (int ni = 0; ni < 8; ni++) {
            int c0 = wn + ni * 8 + lc;
            stg[r0 * STG_STRIDE + c0]           = acc[mi][ni][0];
            stg[r0 * STG_STRIDE + c0 + 1]       = acc[mi][ni][1];
            stg[(r0 + 8) * STG_STRIDE + c0]     = acc[mi][ni][2];
            stg[(r0 + 8) * STG_STRIDE + c0 + 1] = acc[mi][ni][3];
        }
    }
    __syncthreads();
#pragma unroll
    for (int i = 0; i < 64; i++) {
        int e = tid + i * 256;             // 0..16383
        int r = e >> 7, c = e & 127;       // consecutive lanes -> consecutive c
        int col = n0 + c;
        if (col < V_SIZE)
            C[(size_t)(m0 + r) * V_SIZE + col] = stg[r * STG_STRIDE + c];
    }
}

// ---------------- kernel 2: fp16 q+k projections (mma.sync, z selects) --------
__global__ __launch_bounds__(256)
void qkproj_kernel(const __half* __restrict__ xh) {
    extern __shared__ char smem[];
    const uint32_t sb = smem_u32(smem);

    const __half* W = blockIdx.z ? g_wkh : g_wqh;
    __half* O = blockIdx.z ? g_kh : g_qh;

    const int tid = threadIdx.x;
    const int wid = tid >> 5;
    const int lane = tid & 31;
    const int m0 = blockIdx.x * BM;
    const int n0 = blockIdx.y * BN;

    const int wm = (wid & 3) * 32;
    const int wn = (wid >> 2) * 64;

    float acc[2][8][4];
#pragma unroll
    for (int mi = 0; mi < 2; mi++)
#pragma unroll
        for (int ni = 0; ni < 8; ni++)
#pragma unroll
            for (int q = 0; q < 4; q++) acc[mi][ni][q] = 0.f;

    auto load_stage = [&](int kit, int slot) {
        int kbase = kit * BK;
        uint32_t st = sb + slot * STAGE_BYTES;
        uint32_t as = st, bs = st + 16384;
#pragma unroll
        for (int j = 0; j < 4; j++) {
            int id = tid + j * 256;
            int r = id >> 3, c = id & 7;
            cp16(as + swz(r, c), xh + (size_t)(m0 + r) * E_SIZE + kbase + c * 8);
        }
#pragma unroll
        for (int j = 0; j < 4; j++) {
            int id = tid + j * 256;
            int r = id >> 3, c = id & 7;
            cp16(bs + swz(r, c), W + (size_t)(n0 + r) * E_SIZE + kbase + c * 8);
        }
        CP_COMMIT();
    };

    load_stage(0, 0);
    load_stage(1, 1);

    const int lrl = lane & 7;
    const int lmat = lane >> 3;

    for (int t = 0; t < KIT; t++) {
        if (t < KIT - 2) { CP_WAIT1(); } else { CP_WAIT0(); }
        __syncthreads();
        uint32_t st = sb + (t & 1) * STAGE_BYTES;
        uint32_t a_s = st, b_s = st + 16384;

#pragma unroll
        for (int kk = 0; kk < 4; kk++) {
            int cbase = kk * 2;
            uint32_t bfr[8][2];
#pragma unroll
            for (int pr = 0; pr < 4; pr++) {
                int r = wn + pr * 16 + lrl + (lmat >> 1) * 8;
                int c = cbase + (lmat & 1);
                uint32_t q0, q1, q2, q3;
                ldsm_x4(q0, q1, q2, q3, b_s + swz(r, c));
                bfr[pr * 2 + 0][0] = q0; bfr[pr * 2 + 0][1] = q1;
                bfr[pr * 2 + 1][0] = q2; bfr[pr * 2 + 1][1] = q3;
            }
            uint32_t afr[2][4];
#pragma unroll
            for (int mi = 0; mi < 2; mi++) {
                int r = wm + mi * 16 + lrl + (lmat & 1) * 8;
                int c = cbase + (lmat >> 1);
                ldsm_x4(afr[mi][0], afr[mi][1], afr[mi][2], afr[mi][3], a_s + swz(r, c));
            }
#pragma unroll
            for (int mi = 0; mi < 2; mi++)
#pragma unroll
                for (int ni = 0; ni < 8; ni++)
                    mma16816(acc[mi][ni], afr[mi], bfr[ni]);
        }
        __syncthreads();
        if (t + 2 < KIT) load_stage(t + 2, t & 1);
    }

    const int lr = lane >> 2;
    const int lc = (lane & 3) * 2;
#pragma unroll
    for (int mi = 0; mi < 2; mi++) {
        int row0 = m0 + wm + mi * 16 + lr;
#pragma unroll
        for (int ni = 0; ni < 8; ni++) {
            int col = n0 + wn + ni * 8 + lc;
            *(__half2*)(O + (size_t)row0 * QK_SIZE + col) =
                __floats2half2_rn(acc[mi][ni][0], acc[mi][ni][1]);
            *(__half2*)(O + (size_t)(row0 + 8) * QK_SIZE + col) =
                __floats2half2_rn(acc[mi][ni][2], acc[mi][ni][3]);
        }
    }
}

// ---------------- kernel 3: fused c = q k^T / QK + scatter-add into logits ----
__global__ __launch_bounds__(256)
void qk_scatter_kernel(const int* __restrict__ idx, float* __restrict__ logits) {
    extern __shared__ char smem[];
    const uint32_t sb = smem_u32(smem);
    __shared__ int ibs[128];

    int bx = blockIdx.x;
    int b = bx / 36;
    int p = bx % 36;
    int mt = 0;
    while ((mt + 1) * (mt + 2) / 2 <= p) mt++;
    int nt = p - mt * (mt + 1) / 2;

    const int tid = threadIdx.x;
    const int wid = tid >> 5;
    const int lane = tid & 31;
    const int m0 = b * T_SIZE + mt * 128;
    const int n0 = b * T_SIZE + nt * 128;

    if (tid < 128) ibs[tid] = idx[n0 + tid];

    const int wm = (wid & 3) * 32;
    const int wn = (wid >> 2) * 64;

    float acc[2][8][4];
#pragma unroll
    for (int mi = 0; mi < 2; mi++)
#pragma unroll
        for (int ni = 0; ni < 8; ni++)
#pragma unroll
            for (int q = 0; q < 4; q++) acc[mi][ni][q] = 0.f;

    auto load_stage = [&](int kit, int slot) {
        int kbase = kit * BK;
        uint32_t st = sb + slot * STAGE_BYTES;
        uint32_t as = st, bs = st + 16384;
#pragma unroll
        for (int j = 0; j < 4; j++) {
            int id = tid + j * 256;
            int r = id >> 3, c = id & 7;
            cp16(as + swz(r, c), g_qh + (size_t)(m0 + r) * QK_SIZE + kbase + c * 8);
        }
#pragma unroll
        for (int j = 0; j < 4; j++) {
            int id = tid + j * 256;
            int r = id >> 3, c = id & 7;
            cp16(bs + swz(r, c), g_kh + (size_t)(n0 + r) * QK_SIZE + kbase + c * 8);
        }
        CP_COMMIT();
    };

    load_stage(0, 0);
    load_stage(1, 1);

    const int lrl = lane & 7;
    const int lmat = lane >> 3;

    for (int t = 0; t < KIT_QK; t++) {
        if (t < KIT_QK - 2) { CP_WAIT1(); } else { CP_WAIT0(); }
        __syncthreads();
        uint32_t st = sb + (t & 1) * STAGE_BYTES;
        uint32_t a_s = st, b_s = st + 16384;

#pragma unroll
        for (int kk = 0; kk < 4; kk++) {
            int cbase = kk * 2;
            uint32_t bfr[8][2];
#pragma unroll
            for (int pr = 0; pr < 4; pr++) {
                int r = wn + pr * 16 + lrl + (lmat >> 1) * 8;
                int c = cbase + (lmat & 1);
                uint32_t q0, q1, q2, q3;
                ldsm_x4(q0, q1, q2, q3, b_s + swz(r, c));
                bfr[pr * 2 + 0][0] = q0; bfr[pr * 2 + 0][1] = q1;
                bfr[pr * 2 + 1][0] = q2; bfr[pr * 2 + 1][1] = q3;
            }
            uint32_t afr[2][4];
#pragma unroll
            for (int mi = 0; mi < 2; mi++) {
                int r = wm + mi * 16 + lrl + (lmat & 1) * 8;
                int c = cbase + (lmat >> 1);
                ldsm_x4(afr[mi][0], afr[mi][1], afr[mi][2], afr[mi][3], a_s + swz(r, c));
            }
#pragma unroll
            for (int mi = 0; mi < 2; mi++)
#pragma unroll
                for (int ni = 0; ni < 8; ni++)
                    mma16816(acc[mi][ni], afr[mi], bfr[ni]);
        }
        __syncthreads();
        if (t + 2 < KIT_QK) load_stage(t + 2, t & 1);
    }

    const int lr = lane >> 2;
    const int lc = (lane & 3) * 2;
    const float sc = 1.0f / QK_SIZE;
#pragma unroll
    for (int mi = 0; mi < 2; mi++) {
        int tl0 = mt * 128 + wm + mi * 16 + lr;
#pragma unroll
        for (int ni = 0; ni < 8; ni++) {
            int cl = wn + ni * 8 + lc;
            int sl = nt * 128 + cl;
            float* l0 = logits + (size_t)(b * T_SIZE + tl0) * V_SIZE;
            float* l1 = logits + (size_t)(b * T_SIZE + tl0 + 8) * V_SIZE;
            int v0 = ibs[cl], v1 = ibs[cl + 1];
            if (sl <= tl0)         atomicAdd(l0 + v0, acc[mi][ni][0] * sc);
            if (sl + 1 <= tl0)     atomicAdd(l0 + v1, acc[mi][ni][1] * sc);
            if (sl <= tl0 + 8)     atomicAdd(l1 + v0, acc[mi][ni][2] * sc);
            if (sl + 1 <= tl0 + 8) atomicAdd(l1 + v1, acc[mi][ni][3] * sc);
        }
    }
}

// ---------------- launch ----------------
extern "C" void kernel_launch(void* const* d_in, const int* in_sizes, int n_in,
                              void* d_out, int out_size) {
    const int*   idx    = (const int*)d_in[0];
    const float* emb_w  = (const float*)d_in[1];
    const float* ln_g   = (const float*)d_in[2];
    const float* ln_b   = (const float*)d_in[3];
    const float* head_w = (const float*)d_in[4];
    const float* head_q = (const float*)d_in[5];
    const float* head_k = (const float*)d_in[6];

    void *pxh, *pwh;
    cudaGetSymbolAddress(&pxh, g_xh);
    cudaGetSymbolAddress(&pwh, g_wh);

    float* out    = (float*)d_out;
    float* logits = out;

    const size_t logits_elems = (size_t)M_ROWS * V_SIZE;
    const size_t x_elems      = (size_t)M_ROWS * E_SIZE;
    float* xout = nullptr;
    if ((size_t)out_size >= logits_elems + x_elems)
        xout = out + ((size_t)out_size - x_elems);

    // 1) x = layernorm(emb[idx]) (fp16 x + fp32 xout)
    ln_kernel<<<M_ROWS, 256>>>(idx, emb_w, ln_g, ln_b, xout);

    // 1b) head_w -> fp16 ; head_q/head_k -> fp16
    {
        size_t n2 = (size_t)V_SIZE * E_SIZE / 2;
        wsplit_kernel<<<(unsigned)((n2 + 255) / 256), 256>>>(head_w);
        int m2 = QK_SIZE * E_SIZE / 2;
        wqk_kernel<<<(m2 + 255) / 256, 256>>>(head_q, head_k);
    }

    // 2) q,k projections via fp16 mma.sync (outputs fp16)
    {
        cudaFuncSetAttribute(qkproj_kernel, cudaFuncAttributeMaxDynamicSharedMemorySize, SMEM_DYN);
        dim3 grid(M_ROWS / BM, QK_SIZE / BN, 2);
        qkproj_kernel<<<grid, 256, SMEM_DYN>>>((const __half*)pxh);
    }

    // 3) logits = x @ head_w^T via single-pass fp16 mma.sync (staged epilogue)
    {
        cudaFuncSetAttribute(mma_gemm_kernel, cudaFuncAttributeMaxDynamicSharedMemorySize, SMEM_DYN);
        dim3 grid(M_ROWS / BM, (V_SIZE + BN - 1) / BN);
        mma_gemm_kernel<<<grid, 256, SMEM_DYN>>>(
            (const __half*)pxh, (const __half*)pwh, logits);
    }

    // 4) fused causal qk^T + copy-scatter into logits
    {
        cudaFuncSetAttribute(qk_scatter_kernel, cudaFuncAttributeMaxDynamicSharedMemorySize, SMEM_DYN);
        qk_scatter_kernel<<<B_SIZE * 36, 256, SMEM_DYN>>>(idx, logits);
    }
}